// round 13
// baseline (speedup 1.0000x reference)
#include <cuda_runtime.h>
#include <math.h>
#include <stdint.h>

#define BNUM 32
#define LLT 512
#define LST 128
#define CIN 9
#define HDIM 128
#define RNUM 8
#define KWIN 25
#define PADW 12
#define EPSF 1e-5f
#define OUTC 192   // M*3
#define NHTOT 16384  // LST*HDIM
#define NCHUNK 64    // nh chunks of 256

typedef unsigned long long u64;

// -------- scratch (static device, no allocs) --------
__device__ float d_bufA[BNUM*LLT*HDIM];
__device__ float d_bufB[BNUM*LLT*HDIM];
__device__ float d_est [BNUM*LST*HDIM];
__device__ float d_gbuf[8*BNUM*HDIM*256];   // K-split partials for lb1, 32MB
__device__ float d_logits[BNUM*RNUM];
__device__ float d_wsel[BNUM];
__device__ int   d_rcount[RNUM];
__device__ int   d_rlist[RNUM*BNUM];
__device__ float d_partial[BNUM*NCHUNK*OUTC];

// -------- f32x2 packed math helpers --------
__device__ __forceinline__ u64 pack2(float lo, float hi){
    u64 d;
    asm("mov.b64 %0, {%1, %2};" : "=l"(d)
        : "r"(__float_as_uint(lo)), "r"(__float_as_uint(hi)));
    return d;
}
__device__ __forceinline__ void unpack2(u64 v, float& lo, float& hi){
    uint32_t a, b;
    asm("mov.b64 {%0, %1}, %2;" : "=r"(a), "=r"(b) : "l"(v));
    lo = __uint_as_float(a); hi = __uint_as_float(b);
}
__device__ __forceinline__ void ffma2(u64& d, u64 a, u64 b, u64 c){
    asm("fma.rn.f32x2 %0, %1, %2, %3;" : "=l"(d) : "l"(a), "l"(b), "l"(c));
}

__device__ __forceinline__ float gelu_exact(float x){
    return 0.5f*x*(1.0f+erff(x*0.7071067811865476f));
}

// shuffle-reduce a value over SPAN contiguous lanes (SPAN = power of 2 <= 32)
template<int SPAN>
__device__ __forceinline__ float span_reduce(float v){
    #pragma unroll
    for (int o=SPAN/2; o; o>>=1) v += __shfl_xor_sync(0xffffffffu, v, o);
    return v;
}

// reduce 4 values over the NQ threads of each tid-contiguous group (32/64/128/256)
template<int NQ>
__device__ __forceinline__ void grp_reduce4(float v[4], float* buf, int tid){
    #pragma unroll
    for (int i=0;i<4;i++) v[i] = span_reduce<32>(v[i]);
    if (NQ > 32){
        constexpr int NWG = NQ/32;
        int wid = tid>>5, lane = tid&31;
        if (lane==0){
            #pragma unroll
            for (int i=0;i<4;i++) buf[wid*4+i] = v[i];
        }
        __syncthreads();
        int gw0 = (wid/NWG)*NWG;
        #pragma unroll
        for (int i=0;i<4;i++){
            float s = 0.f;
            #pragma unroll
            for (int w=0;w<NWG;w++) s += buf[(gw0+w)*4+i];
            v[i] = s;
        }
        __syncthreads();
    }
}

// ---------------- encode (merged lt+st): warp-per-l ----------------
__global__ void encode_kernel(const float* __restrict__ in_lt, const float* __restrict__ in_st,
                              const float* __restrict__ Ws, const float* __restrict__ bs,
                              const float* __restrict__ Wt, const float* __restrict__ bt,
                              float* __restrict__ out_lt, float* __restrict__ out_st){
    int b = blockIdx.y;
    int w = threadIdx.x >> 5, lane = threadIdx.x & 31;
    const float* in; float* out; int L; int lx;
    if (blockIdx.x < LLT/4){ in = in_lt; out = out_lt; L = LLT; lx = blockIdx.x; }
    else                   { in = in_st; out = out_st; L = LST; lx = blockIdx.x - LLT/4; }
    int l = lx*4 + w;
    const float* base = in + (size_t)b*L*CIN;
    float sxl = 0.f, txl = 0.f;
    if (lane < CIN){
        int c = lane;
        float x0 = base[c];
        float xl = base[l*CIN + c];
        float sum = 0.f;
        #pragma unroll
        for (int k=0; k<KWIN; k++){
            int l2 = l - PADW + k;
            l2 = l2 < 0 ? 0 : (l2 > L-1 ? L-1 : l2);
            sum += base[l2*CIN + c];
        }
        float mavg = sum*(1.0f/KWIN);
        sxl = xl - mavg;
        txl = mavg - x0;
    }
    float sx[CIN], tx[CIN];
    #pragma unroll
    for (int c=0;c<CIN;c++){
        sx[c] = __shfl_sync(0xffffffffu, sxl, c);
        tx[c] = __shfl_sync(0xffffffffu, txl, c);
    }
    int h0 = lane*4;
    float4 bsv = *(const float4*)(bs + h0);
    float4 btv = *(const float4*)(bt + h0);
    float s4[4] = {bsv.x, bsv.y, bsv.z, bsv.w};
    float t4[4] = {btv.x, btv.y, btv.z, btv.w};
    #pragma unroll
    for (int c=0;c<CIN;c++){
        float4 wsv = *(const float4*)(Ws + c*HDIM + h0);
        float4 wtv = *(const float4*)(Wt + c*HDIM + h0);
        s4[0]=fmaf(sx[c],wsv.x,s4[0]); s4[1]=fmaf(sx[c],wsv.y,s4[1]);
        s4[2]=fmaf(sx[c],wsv.z,s4[2]); s4[3]=fmaf(sx[c],wsv.w,s4[3]);
        t4[0]=fmaf(tx[c],wtv.x,t4[0]); t4[1]=fmaf(tx[c],wtv.y,t4[1]);
        t4[2]=fmaf(tx[c],wtv.z,t4[2]); t4[3]=fmaf(tx[c],wtv.w,t4[3]);
    }
    float ss = span_reduce<32>(s4[0]+s4[1]+s4[2]+s4[3]);
    float ts = span_reduce<32>(t4[0]+t4[1]+t4[2]+t4[3]);
    float ms = ss*(1.0f/HDIM), mt = ts*(1.0f/HDIM);
    float ds[4], dt[4];
    float sqs = 0.f, sqt = 0.f;
    #pragma unroll
    for (int i=0;i<4;i++){
        ds[i]=s4[i]-ms; dt[i]=t4[i]-mt;
        sqs = fmaf(ds[i],ds[i],sqs); sqt = fmaf(dt[i],dt[i],sqt);
    }
    sqs = span_reduce<32>(sqs);
    sqt = span_reduce<32>(sqt);
    float rs = rsqrtf(sqs*(1.0f/HDIM)+EPSF);
    float rt = rsqrtf(sqt*(1.0f/HDIM)+EPSF);
    float4 y;
    y.x = gelu_exact(ds[0]*rs) + gelu_exact(dt[0]*rt);
    y.y = gelu_exact(ds[1]*rs) + gelu_exact(dt[1]*rt);
    y.z = gelu_exact(ds[2]*rs) + gelu_exact(dt[2]*rt);
    y.w = gelu_exact(ds[3]*rs) + gelu_exact(dt[3]*rt);
    *(float4*)(out + ((size_t)b*L + l)*HDIM + h0) = y;
}

// ================ fused hidden: GEMM(MT=32 x N=128 full-j) + bias + inorm_j + gelu ================
template<int M>
__global__ __launch_bounds__(256) void hidden_fused(const float* __restrict__ A,
                                                    const float* __restrict__ W,
                                                    const float* __restrict__ bias,
                                                    float* __restrict__ out){
    constexpr int K=HDIM, N=HDIM, MT=32, KT=16, NKT=K/KT, AST=MT+8;
    __shared__ __align__(16) float As[2][KT*AST];
    __shared__ __align__(16) float Bs[2][KT*N];
    int tid = threadIdx.x;
    int tn = tid & 31, tm = tid >> 5;
    int m0 = blockIdx.x*MT;
    int b  = blockIdx.z;
    const float* Ab = A + (size_t)b*M*K;
    int fm = tid>>2, fq = tid&3;
    {
        if (tid < 128){
            float4 pa = *(const float4*)(Ab + (size_t)(m0+fm)*K + 4*fq);
            As[0][(4*fq+0)*AST+fm]=pa.x; As[0][(4*fq+1)*AST+fm]=pa.y;
            As[0][(4*fq+2)*AST+fm]=pa.z; As[0][(4*fq+3)*AST+fm]=pa.w;
        }
        #pragma unroll
        for (int e=0;e<2;e++){
            int q = tid + e*256;
            int fk = q>>5, ff = q&31;
            *(float4*)(Bs[0] + fk*N + 4*ff) = *(const float4*)(W + (size_t)fk*N + 4*ff);
        }
    }
    __syncthreads();
    u64 acc[4][2];
    #pragma unroll
    for (int mi=0;mi<4;mi++){ acc[mi][0]=0ull; acc[mi][1]=0ull; }
    for (int kt=0; kt<NKT; kt++){
        int cur = kt & 1;
        bool hasnext = (kt+1 < NKT);
        float4 pa, pb0, pb1;
        if (hasnext){
            int kn = (kt+1)*KT;
            if (tid < 128) pa = *(const float4*)(Ab + (size_t)(m0+fm)*K + kn + 4*fq);
            { int q=tid;     int fk=q>>5, ff=q&31; pb0 = *(const float4*)(W + (size_t)(kn+fk)*N + 4*ff); }
            { int q=tid+256; int fk=q>>5, ff=q&31; pb1 = *(const float4*)(W + (size_t)(kn+fk)*N + 4*ff); }
        }
        const float* Asb = As[cur];
        const float* Bsb = Bs[cur];
        #pragma unroll
        for (int kk=0; kk<KT; kk++){
            float4 av = *(const float4*)(Asb + kk*AST + 4*tm);
            float4 bv = *(const float4*)(Bsb + kk*N + 4*tn);
            u64 b01 = pack2(bv.x, bv.y);
            u64 b23 = pack2(bv.z, bv.w);
            u64 a0 = pack2(av.x, av.x);
            u64 a1 = pack2(av.y, av.y);
            u64 a2 = pack2(av.z, av.z);
            u64 a3 = pack2(av.w, av.w);
            ffma2(acc[0][0], a0, b01, acc[0][0]); ffma2(acc[0][1], a0, b23, acc[0][1]);
            ffma2(acc[1][0], a1, b01, acc[1][0]); ffma2(acc[1][1], a1, b23, acc[1][1]);
            ffma2(acc[2][0], a2, b01, acc[2][0]); ffma2(acc[2][1], a2, b23, acc[2][1]);
            ffma2(acc[3][0], a3, b01, acc[3][0]); ffma2(acc[3][1], a3, b23, acc[3][1]);
        }
        if (hasnext){
            int nxt = cur ^ 1;
            __syncthreads();
            if (tid < 128){
                As[nxt][(4*fq+0)*AST+fm]=pa.x; As[nxt][(4*fq+1)*AST+fm]=pa.y;
                As[nxt][(4*fq+2)*AST+fm]=pa.z; As[nxt][(4*fq+3)*AST+fm]=pa.w;
            }
            { int q=tid;     int fk=q>>5, ff=q&31; *(float4*)(Bs[nxt] + fk*N + 4*ff) = pb0; }
            { int q=tid+256; int fk=q>>5, ff=q&31; *(float4*)(Bs[nxt] + fk*N + 4*ff) = pb1; }
            __syncthreads();
        }
    }
    float4 bj = *(const float4*)(bias + 4*tn);
    float* ob = out + (size_t)b*M*N;
    #pragma unroll
    for (int mi=0;mi<4;mi++){
        float v0,v1,v2,v3;
        unpack2(acc[mi][0], v0, v1);
        unpack2(acc[mi][1], v2, v3);
        v0+=bj.x; v1+=bj.y; v2+=bj.z; v3+=bj.w;
        float mean = span_reduce<32>(v0+v1+v2+v3)*(1.0f/N);
        float d0=v0-mean, d1=v1-mean, d2=v2-mean, d3=v3-mean;
        float var = span_reduce<32>(fmaf(d0,d0,fmaf(d1,d1,fmaf(d2,d2,d3*d3))))*(1.0f/N);
        float rv = rsqrtf(var+EPSF);
        float4 o;
        o.x=gelu_exact(d0*rv); o.y=gelu_exact(d1*rv);
        o.z=gelu_exact(d2*rv); o.w=gelu_exact(d3*rv);
        *(float4*)(ob + (size_t)(m0 + 4*tm + mi)*N + 4*tn) = o;
    }
}

// ================ fused lookback: GEMM(full-N tile) + bias + inorm_j + gelu + transpose ================
template<int N, int K>
__global__ __launch_bounds__(256) void lookback_fused(const float* __restrict__ A,
                                                      const float* __restrict__ W,
                                                      const float* __restrict__ bias,
                                                      float* __restrict__ out){
    constexpr int M=HDIM, NQJ=N/4, MT=4096/N, KT=16, NKT=K/KT, AST=MT+8, TSS=MT+8;
    constexpr int AQ = MT/4;
    __shared__ __align__(16) float As[2][KT*AST];
    __shared__ __align__(16) float Bs[2][KT*N];
    __shared__ __align__(16) float Ts[N*TSS];
    int tid = threadIdx.x;
    int tn = tid % NQJ, tm = tid / NQJ;
    int m0 = blockIdx.x*MT;
    int b  = blockIdx.z;
    const float* Ab = A + (size_t)b*K*M;
    {
        #pragma unroll
        for (int e=tid; e<KT*AQ; e+=256){
            int fk = e/AQ, ff = e%AQ;
            *(float4*)(As[0] + fk*AST + 4*ff) = *(const float4*)(Ab + (size_t)fk*M + m0 + 4*ff);
        }
        #pragma unroll
        for (int e=tid; e<KT*N/4; e+=256){
            int fk = e/(N/4), ff = e%(N/4);
            *(float4*)(Bs[0] + fk*N + 4*ff) = *(const float4*)(W + (size_t)fk*N + 4*ff);
        }
    }
    __syncthreads();
    u64 acc[4][2];
    #pragma unroll
    for (int mi=0;mi<4;mi++){ acc[mi][0]=0ull; acc[mi][1]=0ull; }
    for (int kt=0; kt<NKT; kt++){
        int cur = kt & 1;
        bool hasnext = (kt+1 < NKT);
        float4 pa[(KT*AQ+255)/256], pb[(KT*N/4+255)/256];
        if (hasnext){
            int kn = (kt+1)*KT;
            #pragma unroll
            for (int e=0;e<(KT*AQ+255)/256;e++){
                int q = tid + e*256;
                if (q < KT*AQ){
                    int fk=q/AQ, ff=q%AQ;
                    pa[e] = *(const float4*)(Ab + (size_t)(kn+fk)*M + m0 + 4*ff);
                }
            }
            #pragma unroll
            for (int e=0;e<(KT*N/4+255)/256;e++){
                int q = tid + e*256;
                if (q < KT*N/4){
                    int fk=q/(N/4), ff=q%(N/4);
                    pb[e] = *(const float4*)(W + (size_t)(kn+fk)*N + 4*ff);
                }
            }
        }
        const float* Asb = As[cur];
        const float* Bsb = Bs[cur];
        #pragma unroll
        for (int kk=0; kk<KT; kk++){
            float4 av = *(const float4*)(Asb + kk*AST + 4*tm);
            float4 bv = *(const float4*)(Bsb + kk*N + 4*tn);
            u64 b01 = pack2(bv.x, bv.y);
            u64 b23 = pack2(bv.z, bv.w);
            u64 a0 = pack2(av.x, av.x);
            u64 a1 = pack2(av.y, av.y);
            u64 a2 = pack2(av.z, av.z);
            u64 a3 = pack2(av.w, av.w);
            ffma2(acc[0][0], a0, b01, acc[0][0]); ffma2(acc[0][1], a0, b23, acc[0][1]);
            ffma2(acc[1][0], a1, b01, acc[1][0]); ffma2(acc[1][1], a1, b23, acc[1][1]);
            ffma2(acc[2][0], a2, b01, acc[2][0]); ffma2(acc[2][1], a2, b23, acc[2][1]);
            ffma2(acc[3][0], a3, b01, acc[3][0]); ffma2(acc[3][1], a3, b23, acc[3][1]);
        }
        if (hasnext){
            int nxt = cur ^ 1;
            __syncthreads();
            #pragma unroll
            for (int e=0;e<(KT*AQ+255)/256;e++){
                int q = tid + e*256;
                if (q < KT*AQ){
                    int fk=q/AQ, ff=q%AQ;
                    *(float4*)(As[nxt] + fk*AST + 4*ff) = pa[e];
                }
            }
            #pragma unroll
            for (int e=0;e<(KT*N/4+255)/256;e++){
                int q = tid + e*256;
                if (q < KT*N/4){
                    int fk=q/(N/4), ff=q%(N/4);
                    *(float4*)(Bs[nxt] + fk*N + 4*ff) = pb[e];
                }
            }
            __syncthreads();
        }
    }
    float4 bj = *(const float4*)(bias + 4*tn);
    #pragma unroll
    for (int mi=0;mi<4;mi++){
        float v0,v1,v2,v3;
        unpack2(acc[mi][0], v0, v1);
        unpack2(acc[mi][1], v2, v3);
        v0+=bj.x; v1+=bj.y; v2+=bj.z; v3+=bj.w;
        float mean = span_reduce<NQJ>(v0+v1+v2+v3)*(1.0f/N);
        float d0=v0-mean, d1=v1-mean, d2=v2-mean, d3=v3-mean;
        float var = span_reduce<NQJ>(fmaf(d0,d0,fmaf(d1,d1,fmaf(d2,d2,d3*d3))))*(1.0f/N);
        float rv = rsqrtf(var+EPSF);
        int h = 4*tm + mi;
        Ts[(4*tn+0)*TSS + h] = gelu_exact(d0*rv);
        Ts[(4*tn+1)*TSS + h] = gelu_exact(d1*rv);
        Ts[(4*tn+2)*TSS + h] = gelu_exact(d2*rv);
        Ts[(4*tn+3)*TSS + h] = gelu_exact(d3*rv);
    }
    __syncthreads();
    #pragma unroll
    for (int e=tid; e<N*AQ; e+=256){
        int j = e/AQ, hq = e%AQ;
        float4 v = *(const float4*)(Ts + j*TSS + 4*hq);
        *(float4*)(out + ((size_t)b*N + j)*HDIM + m0 + 4*hq) = v;
    }
}

// ================ generic GEMM (lb1): D_z[m][n] = sum_k A_b[k][m]*B[k][n] ================
template<int M, int N, int K, int KS>
__global__ __launch_bounds__(256) void gemm_kernel(const float* __restrict__ A,
                                                   const float* __restrict__ B,
                                                   float* __restrict__ D){
    constexpr int MT=64, NT=64, KT=16;
    constexpr int KC = K/KS;
    constexpr int NKT = KC/KT;
    constexpr int AST = MT+4;
    __shared__ __align__(16) float As[2][KT*AST];
    __shared__ __align__(16) float Bs[2][KT*NT];
    int tid = threadIdx.x;
    int tn = tid & 15, tm = tid >> 4;
    int m0 = blockIdx.x * MT, n0 = blockIdx.y * NT;
    int z = blockIdx.z;
    int b = z / KS, ks = z % KS;
    int k0 = ks * KC;
    const float* Ab = A + (size_t)b*K*M;
    int fk = tid >> 4, ff = tid & 15;
    {
        float4 pa = *(const float4*)(Ab + (size_t)(k0 + fk)*M + m0 + 4*ff);
        float4 pb = *(const float4*)(B + (size_t)(k0 + fk)*N + n0 + 4*ff);
        *(float4*)(As[0] + fk*AST + 4*ff) = pa;
        *(float4*)(Bs[0] + fk*NT + 4*ff) = pb;
    }
    __syncthreads();
    u64 acc[4][2];
    #pragma unroll
    for (int mi=0;mi<4;mi++){ acc[mi][0]=0ull; acc[mi][1]=0ull; }
    for (int kt=0; kt<NKT; kt++){
        int cur = kt & 1;
        bool hasnext = (kt+1 < NKT);
        float4 pa, pb;
        if (hasnext){
            int kn = k0 + (kt+1)*KT;
            pa = *(const float4*)(Ab + (size_t)(kn + fk)*M + m0 + 4*ff);
            pb = *(const float4*)(B + (size_t)(kn + fk)*N + n0 + 4*ff);
        }
        const float* Asb = As[cur];
        const float* Bsb = Bs[cur];
        #pragma unroll
        for (int kk=0; kk<KT; kk++){
            float4 av = *(const float4*)(Asb + kk*AST + 4*tm);
            float4 bv = *(const float4*)(Bsb + kk*NT + 4*tn);
            u64 b01 = pack2(bv.x, bv.y);
            u64 b23 = pack2(bv.z, bv.w);
            u64 a0 = pack2(av.x, av.x);
            u64 a1 = pack2(av.y, av.y);
            u64 a2 = pack2(av.z, av.z);
            u64 a3 = pack2(av.w, av.w);
            ffma2(acc[0][0], a0, b01, acc[0][0]); ffma2(acc[0][1], a0, b23, acc[0][1]);
            ffma2(acc[1][0], a1, b01, acc[1][0]); ffma2(acc[1][1], a1, b23, acc[1][1]);
            ffma2(acc[2][0], a2, b01, acc[2][0]); ffma2(acc[2][1], a2, b23, acc[2][1]);
            ffma2(acc[3][0], a3, b01, acc[3][0]); ffma2(acc[3][1], a3, b23, acc[3][1]);
        }
        if (hasnext){
            int nxt = cur ^ 1;
            __syncthreads();
            *(float4*)(As[nxt] + fk*AST + 4*ff) = pa;
            *(float4*)(Bs[nxt] + fk*NT + 4*ff) = pb;
            __syncthreads();
        }
    }
    float* Dz = D + (size_t)(ks*BNUM + b) * M * N;
    #pragma unroll
    for (int mi=0; mi<4; mi++){
        float4 o;
        unpack2(acc[mi][0], o.x, o.y);
        unpack2(acc[mi][1], o.z, o.w);
        *(float4*)(Dz + (size_t)(m0 + 4*tm + mi)*N + n0 + 4*tn) = o;
    }
}

// ---------------- lookback finalize (lb1 only) ----------------
template<int LOUT, int KS>
__global__ void lookback_finalize(const float* __restrict__ part, const float* __restrict__ bias,
                                  float* __restrict__ out){
    int t = threadIdx.x;
    int h0 = blockIdx.x*4;
    int b  = blockIdx.y;
    __shared__ float rbuf[(LOUT/32)*4];
    float bj = bias[t];
    float val[4];
    #pragma unroll
    for (int h=0;h<4;h++){
        float s = bj;
        #pragma unroll
        for (int ks=0;ks<KS;ks++)
            s += part[((size_t)(ks*BNUM + b)*HDIM + h0 + h)*LOUT + t];
        val[h]=s;
    }
    float v[4] = {val[0],val[1],val[2],val[3]};
    grp_reduce4<LOUT>(v, rbuf, t);
    float d[4];
    #pragma unroll
    for (int h=0;h<4;h++) d[h] = val[h] - v[h]*(1.0f/LOUT);
    float v2[4] = {d[0]*d[0], d[1]*d[1], d[2]*d[2], d[3]*d[3]};
    grp_reduce4<LOUT>(v2, rbuf, t);
    float4 o;
    o.x = gelu_exact(d[0]*rsqrtf(v2[0]*(1.0f/LOUT)+EPSF));
    o.y = gelu_exact(d[1]*rsqrtf(v2[1]*(1.0f/LOUT)+EPSF));
    o.z = gelu_exact(d[2]*rsqrtf(v2[2]*(1.0f/LOUT)+EPSF));
    o.w = gelu_exact(d[3]*rsqrtf(v2[3]*(1.0f/LOUT)+EPSF));
    *(float4*)(out + ((size_t)b*LOUT + t)*HDIM + h0) = o;
}

// ---------------- logits ----------------
__global__ void logits_kernel(const float* __restrict__ o, const float* __restrict__ Wr,
                              const float* __restrict__ br, float* __restrict__ logits){
    int b = blockIdx.x, tid = threadIdx.x;
    float acc[8];
    #pragma unroll
    for (int r=0;r<8;r++) acc[r]=0.f;
    for (int i=tid; i<8192; i+=256){
        float x = o[(size_t)b*8192 + i];
        const float4* w4 = reinterpret_cast<const float4*>(Wr + (size_t)i*8);
        float4 wa = w4[0], wb = w4[1];
        acc[0]=fmaf(x,wa.x,acc[0]); acc[1]=fmaf(x,wa.y,acc[1]);
        acc[2]=fmaf(x,wa.z,acc[2]); acc[3]=fmaf(x,wa.w,acc[3]);
        acc[4]=fmaf(x,wb.x,acc[4]); acc[5]=fmaf(x,wb.y,acc[5]);
        acc[6]=fmaf(x,wb.z,acc[6]); acc[7]=fmaf(x,wb.w,acc[7]);
    }
    __shared__ float sh[8*8];
    #pragma unroll
    for (int r=0;r<8;r++) acc[r] = span_reduce<32>(acc[r]);
    int w=tid>>5, lane=tid&31;
    if (lane==0){
        #pragma unroll
        for (int r=0;r<8;r++) sh[r*8+w]=acc[r];
    }
    __syncthreads();
    if (tid<8){
        float s=br[tid];
        #pragma unroll
        for (int ww=0;ww<8;ww++) s+=sh[tid*8+ww];
        logits[b*8+tid]=s;
    }
}

// ---------------- exact JAX threefry2x32 (partitionable) gumbel + regime lists ----------------
__device__ __forceinline__ uint32_t rotl32(uint32_t x,int r){ return (x<<r)|(x>>(32-r)); }
__device__ __forceinline__ float gumbel_from_bits(uint32_t bits){
    const float tiny = 1.17549435e-38f;
    float f = __uint_as_float((bits>>9)|0x3f800000u) - 1.0f;
    float u = fmaxf(tiny, f + tiny);
    return -logf(-logf(u));
}
__global__ void gumbel_kernel(const float* __restrict__ logits,
                              float* __restrict__ wsel,
                              int* __restrict__ rcount, int* __restrict__ rlist){
    __shared__ float g[256];
    __shared__ int sreg[BNUM];
    int tid = threadIdx.x;
    {
        uint32_t x0 = 0u, x1 = (uint32_t)tid;
        const uint32_t k0=0u, k1=42u, k2=k0^k1^0x1BD11BDAu;
        x0+=k0; x1+=k1;
        #define TFR(r) { x0+=x1; x1=rotl32(x1,r); x1^=x0; }
        TFR(13)TFR(15)TFR(26)TFR(6)   x0+=k1; x1+=k2+1u;
        TFR(17)TFR(29)TFR(16)TFR(24)  x0+=k2; x1+=k0+2u;
        TFR(13)TFR(15)TFR(26)TFR(6)   x0+=k0; x1+=k1+3u;
        TFR(17)TFR(29)TFR(16)TFR(24)  x0+=k1; x1+=k2+4u;
        TFR(13)TFR(15)TFR(26)TFR(6)   x0+=k2; x1+=k0+5u;
        #undef TFR
        g[tid] = gumbel_from_bits(x0 ^ x1);
    }
    __syncthreads();
    if (tid < BNUM){
        float z[8];
        #pragma unroll
        for (int r=0;r<8;r++) z[r] = logits[tid*8+r] + g[tid*8+r];
        float mx = z[0]; int am = 0;
        #pragma unroll
        for (int r=1;r<8;r++) if (z[r] > mx){ mx=z[r]; am=r; }
        float sum=0.f;
        #pragma unroll
        for (int r=0;r<8;r++) sum += expf(z[r]-mx);
        float y = 1.0f/sum;
        wsel[tid] = (1.0f - y) + y;
        sreg[tid] = am;
    }
    __syncthreads();
    if (tid == 0){
        int cnt[RNUM];
        #pragma unroll
        for (int r=0;r<RNUM;r++) cnt[r]=0;
        for (int b=0;b<BNUM;b++){
            int r = sreg[b];
            rlist[r*BNUM + cnt[r]] = b;
            cnt[r]++;
        }
        #pragma unroll
        for (int r=0;r<RNUM;r++) rcount[r]=cnt[r];
    }
}

// ---------------- final contraction, regime-grouped ----------------
template<int NP>
__device__ __forceinline__ void fp_body(const u64* __restrict__ es2,
                                        const float* __restrict__ P,
                                        float* __restrict__ partial,
                                        const int* __restrict__ bl,
                                        int nb, int chunk, int t){
    u64 acc[NP];
    #pragma unroll
    for (int q=0;q<NP;q++) acc[q]=0ull;
    #pragma unroll 4
    for (int nh=0; nh<256; nh++){
        float pv = P[(size_t)nh*OUTC];
        u64 pp = pack2(pv, pv);
        const u64* row = es2 + nh*16;
        #pragma unroll
        for (int p=0;p<NP/2;p++){
            ulonglong2 rr = *(const ulonglong2*)(row + 2*p);
            ffma2(acc[2*p],   rr.x, pp, acc[2*p]);
            ffma2(acc[2*p+1], rr.y, pp, acc[2*p+1]);
        }
        if (NP & 1)
            ffma2(acc[NP-1], row[NP-1], pp, acc[NP-1]);
    }
    #pragma unroll
    for (int q=0;q<NP;q++){
        float lo, hi; unpack2(acc[q], lo, hi);
        partial[((size_t)bl[2*q]*NCHUNK + chunk)*OUTC + t] = lo;
        if (2*q+1 < nb)
            partial[((size_t)bl[2*q+1]*NCHUNK + chunk)*OUTC + t] = hi;
    }
}

__global__ void final_partial(const float* __restrict__ est, const float* __restrict__ proto,
                              const int* __restrict__ rcount, const int* __restrict__ rlist,
                              float* __restrict__ partial){
    int chunk = blockIdx.x, r = blockIdx.y, t = threadIdx.x;
    int nb = rcount[r];
    if (nb == 0) return;
    int npair = (nb+1)>>1;
    __shared__ __align__(16) u64 es2[256*16];
    __shared__ int bl[BNUM];
    if (t < BNUM) bl[t] = rlist[r*BNUM + t];
    __syncthreads();
    int nh0 = chunk*256;
    for (int q=0;q<npair;q++){
        int b0 = bl[2*q];
        bool has1 = (2*q+1) < nb;
        const float* e0 = est + (size_t)b0*NHTOT + nh0;
        const float* e1 = has1 ? est + (size_t)bl[2*q+1]*NHTOT + nh0 : e0;
        for (int nh=t; nh<256; nh+=192){
            float lo = e0[nh];
            float hi = has1 ? e1[nh] : 0.f;
            es2[nh*16+q] = pack2(lo, hi);
        }
    }
    __syncthreads();
    const float* P = proto + ((size_t)r*NHTOT + nh0)*OUTC + t;
    switch(npair){
        case 1:  fp_body<1>(es2,P,partial,bl,nb,chunk,t); break;
        case 2:  fp_body<2 >(es2,P,partial,bl,nb,chunk,t); break;
        case 3:  fp_body<3 >(es2,P,partial,bl,nb,chunk,t); break;
        case 4:  fp_body<4 >(es2,P,partial,bl,nb,chunk,t); break;
        case 5:  fp_body<5 >(es2,P,partial,bl,nb,chunk,t); break;
        case 6:  fp_body<6 >(es2,P,partial,bl,nb,chunk,t); break;
        case 7:  fp_body<7 >(es2,P,partial,bl,nb,chunk,t); break;
        case 8:  fp_body<8 >(es2,P,partial,bl,nb,chunk,t); break;
        case 9:  fp_body<9 >(es2,P,partial,bl,nb,chunk,t); break;
        case 10: fp_body<10>(es2,P,partial,bl,nb,chunk,t); break;
        case 11: fp_body<11>(es2,P,partial,bl,nb,chunk,t); break;
        case 12: fp_body<12>(es2,P,partial,bl,nb,chunk,t); break;
        case 13: fp_body<13>(es2,P,partial,bl,nb,chunk,t); break;
        case 14: fp_body<14>(es2,P,partial,bl,nb,chunk,t); break;
        case 15: fp_body<15>(es2,P,partial,bl,nb,chunk,t); break;
        default: fp_body<16>(es2,P,partial,bl,nb,chunk,t); break;
    }
}

__global__ void final_softmax(const float* __restrict__ partial, const float* __restrict__ wsel,
                              float* __restrict__ out){
    int b = blockIdx.x, t = threadIdx.x;
    float s = 0.f;
    #pragma unroll 8
    for (int ch=0; ch<NCHUNK; ch++) s += partial[((size_t)b*NCHUNK+ch)*OUTC + t];
    s *= wsel[b];
    __shared__ float shm[6], shs[6];
    float m = s;
    #pragma unroll
    for (int o=16;o;o>>=1) m = fmaxf(m, __shfl_xor_sync(0xffffffffu, m, o));
    if ((t&31)==0) shm[t>>5]=m;
    __syncthreads();
    m = shm[0];
    #pragma unroll
    for (int w=1;w<6;w++) m = fmaxf(m, shm[w]);
    float e = expf(s-m);
    float su = span_reduce<32>(e);
    if ((t&31)==0) shs[t>>5]=su;
    __syncthreads();
    su = 0.f;
    #pragma unroll
    for (int w=0;w<6;w++) su += shs[w];
    out[(size_t)b*OUTC + t] = e/su;
}

// ---------------- launch ----------------
extern "C" void kernel_launch(void* const* d_in, const int* in_sizes, int n_in,
                              void* d_out, int out_size){
    (void)in_sizes; (void)n_in; (void)out_size;
    const float* in_lt = (const float*)d_in[0];
    const float* in_st = (const float*)d_in[1];
    const float* Ws  = (const float*)d_in[2];  const float* bs  = (const float*)d_in[3];
    const float* Wt  = (const float*)d_in[4];  const float* bt  = (const float*)d_in[5];
    const float* Wh1 = (const float*)d_in[6];  const float* bh1 = (const float*)d_in[7];
    const float* Wl1 = (const float*)d_in[8];  const float* bl1 = (const float*)d_in[9];
    const float* Wh2 = (const float*)d_in[10]; const float* bh2 = (const float*)d_in[11];
    const float* Wl2 = (const float*)d_in[12]; const float* bl2 = (const float*)d_in[13];
    const float* Wh3 = (const float*)d_in[14]; const float* bh3 = (const float*)d_in[15];
    const float* Wl3 = (const float*)d_in[16]; const float* bl3 = (const float*)d_in[17];
    const float* Wr  = (const float*)d_in[18]; const float* br  = (const float*)d_in[19];
    const float* proto = (const float*)d_in[20];

    float *bufA, *bufB, *est, *gbuf, *logits, *wsel, *partial; int *rcount, *rlist;
    cudaGetSymbolAddress((void**)&bufA,    d_bufA);
    cudaGetSymbolAddress((void**)&bufB,    d_bufB);
    cudaGetSymbolAddress((void**)&est,     d_est);
    cudaGetSymbolAddress((void**)&gbuf,    d_gbuf);
    cudaGetSymbolAddress((void**)&logits,  d_logits);
    cudaGetSymbolAddress((void**)&wsel,    d_wsel);
    cudaGetSymbolAddress((void**)&rcount,  d_rcount);
    cudaGetSymbolAddress((void**)&rlist,   d_rlist);
    cudaGetSymbolAddress((void**)&partial, d_partial);

    // merged encode (lt + st segments)
    encode_kernel<<<dim3(LLT/4 + LST/4, BNUM), 128>>>(in_lt, in_st, Ws, bs, Wt, bt, bufA, est);

    // hidden1 fused: M=512 -> bufB
    hidden_fused<512><<<dim3(16,1,BNUM), 256>>>(bufA, Wh1, bh1, bufB);
    // lookback1: M=128(h), N=256(j), K=512(l), KS=8 -> gbuf -> finalize -> bufA
    gemm_kernel<128,256,512,8><<<dim3(2,4,BNUM*8), 256>>>(bufB, Wl1, gbuf);
    lookback_finalize<256,8><<<dim3(HDIM/4,BNUM), 256>>>(gbuf, bl1, bufA);

    // hidden2 fused: M=256
    hidden_fused<256><<<dim3(8,1,BNUM), 256>>>(bufA, Wh2, bh2, bufB);
    // lookback2 fused: N=128, K=256
    lookback_fused<128,256><<<dim3(4,1,BNUM), 256>>>(bufB, Wl2, bl2, bufA);

    // hidden3 fused: M=128
    hidden_fused<128><<<dim3(4,1,BNUM), 256>>>(bufA, Wh3, bh3, bufB);
    // lookback3 fused: N=64, K=128
    lookback_fused<64,128><<<dim3(2,1,BNUM), 256>>>(bufB, Wl3, bl3, bufA);

    logits_kernel<<<BNUM, 256>>>(bufA, Wr, br, logits);
    gumbel_kernel<<<1, 256>>>(logits, wsel, rcount, rlist);

    final_partial<<<dim3(NCHUNK,RNUM), OUTC>>>(est, proto, rcount, rlist, partial);
    final_softmax<<<BNUM, OUTC>>>(partial, wsel, (float*)d_out);
}

// round 15
// speedup vs baseline: 1.0886x; 1.0886x over previous
#include <cuda_runtime.h>
#include <math.h>
#include <stdint.h>

#define BNUM 32
#define LLT 512
#define LST 128
#define CIN 9
#define HDIM 128
#define RNUM 8
#define KWIN 25
#define PADW 12
#define EPSF 1e-5f
#define OUTC 192   // M*3
#define NHTOT 16384  // LST*HDIM
#define NCHUNK 64    // nh chunks of 256

typedef unsigned long long u64;

// -------- scratch (static device, no allocs) --------
__device__ float d_bufA[BNUM*LLT*HDIM];
__device__ float d_bufB[BNUM*LLT*HDIM];
__device__ float d_est [BNUM*LST*HDIM];
__device__ float d_gbuf[4*BNUM*HDIM*256];   // K-split partials for lb1, 16MB
__device__ float d_logits[BNUM*RNUM];
__device__ float d_partial[BNUM*NCHUNK*OUTC];

// -------- f32x2 packed math helpers --------
__device__ __forceinline__ u64 pack2(float lo, float hi){
    u64 d;
    asm("mov.b64 %0, {%1, %2};" : "=l"(d)
        : "r"(__float_as_uint(lo)), "r"(__float_as_uint(hi)));
    return d;
}
__device__ __forceinline__ void unpack2(u64 v, float& lo, float& hi){
    uint32_t a, b;
    asm("mov.b64 {%0, %1}, %2;" : "=r"(a), "=r"(b) : "l"(v));
    lo = __uint_as_float(a); hi = __uint_as_float(b);
}
__device__ __forceinline__ void ffma2(u64& d, u64 a, u64 b, u64 c){
    asm("fma.rn.f32x2 %0, %1, %2, %3;" : "=l"(d) : "l"(a), "l"(b), "l"(c));
}

__device__ __forceinline__ float gelu_exact(float x){
    return 0.5f*x*(1.0f+erff(x*0.7071067811865476f));
}

// shuffle-reduce a value over SPAN contiguous lanes (SPAN = power of 2 <= 32)
template<int SPAN>
__device__ __forceinline__ float span_reduce(float v){
    #pragma unroll
    for (int o=SPAN/2; o; o>>=1) v += __shfl_xor_sync(0xffffffffu, v, o);
    return v;
}

// reduce 4 values over the NQ threads of each tid-contiguous group (32/64/128/256)
template<int NQ>
__device__ __forceinline__ void grp_reduce4(float v[4], float* buf, int tid){
    #pragma unroll
    for (int i=0;i<4;i++) v[i] = span_reduce<32>(v[i]);
    if (NQ > 32){
        constexpr int NWG = NQ/32;
        int wid = tid>>5, lane = tid&31;
        if (lane==0){
            #pragma unroll
            for (int i=0;i<4;i++) buf[wid*4+i] = v[i];
        }
        __syncthreads();
        int gw0 = (wid/NWG)*NWG;
        #pragma unroll
        for (int i=0;i<4;i++){
            float s = 0.f;
            #pragma unroll
            for (int w=0;w<NWG;w++) s += buf[(gw0+w)*4+i];
            v[i] = s;
        }
        __syncthreads();
    }
}

// -------- exact JAX threefry2x32 (partitionable) gumbel --------
__device__ __forceinline__ uint32_t rotl32(uint32_t x,int r){ return (x<<r)|(x>>(32-r)); }
__device__ __forceinline__ float gumbel_idx(uint32_t idx){
    uint32_t x0 = 0u, x1 = idx;
    const uint32_t k0=0u, k1=42u, k2=k0^k1^0x1BD11BDAu;
    x0+=k0; x1+=k1;
    #define TFR(r) { x0+=x1; x1=rotl32(x1,r); x1^=x0; }
    TFR(13)TFR(15)TFR(26)TFR(6)   x0+=k1; x1+=k2+1u;
    TFR(17)TFR(29)TFR(16)TFR(24)  x0+=k2; x1+=k0+2u;
    TFR(13)TFR(15)TFR(26)TFR(6)   x0+=k0; x1+=k1+3u;
    TFR(17)TFR(29)TFR(16)TFR(24)  x0+=k1; x1+=k2+4u;
    TFR(13)TFR(15)TFR(26)TFR(6)   x0+=k2; x1+=k0+5u;
    #undef TFR
    uint32_t bits = x0 ^ x1;
    const float tiny = 1.17549435e-38f;
    float f = __uint_as_float((bits>>9)|0x3f800000u) - 1.0f;
    float u = fmaxf(tiny, f + tiny);
    return -logf(-logf(u));
}

// ---------------- encode (merged lt+st): warp-per-l ----------------
__global__ void encode_kernel(const float* __restrict__ in_lt, const float* __restrict__ in_st,
                              const float* __restrict__ Ws, const float* __restrict__ bs,
                              const float* __restrict__ Wt, const float* __restrict__ bt,
                              float* __restrict__ out_lt, float* __restrict__ out_st){
    int b = blockIdx.y;
    int w = threadIdx.x >> 5, lane = threadIdx.x & 31;
    const float* in; float* out; int L; int lx;
    if (blockIdx.x < LLT/4){ in = in_lt; out = out_lt; L = LLT; lx = blockIdx.x; }
    else                   { in = in_st; out = out_st; L = LST; lx = blockIdx.x - LLT/4; }
    int l = lx*4 + w;
    const float* base = in + (size_t)b*L*CIN;
    float sxl = 0.f, txl = 0.f;
    if (lane < CIN){
        int c = lane;
        float x0 = base[c];
        float xl = base[l*CIN + c];
        float sum = 0.f;
        #pragma unroll
        for (int k=0; k<KWIN; k++){
            int l2 = l - PADW + k;
            l2 = l2 < 0 ? 0 : (l2 > L-1 ? L-1 : l2);
            sum += base[l2*CIN + c];
        }
        float mavg = sum*(1.0f/KWIN);
        sxl = xl - mavg;
        txl = mavg - x0;
    }
    float sx[CIN], tx[CIN];
    #pragma unroll
    for (int c=0;c<CIN;c++){
        sx[c] = __shfl_sync(0xffffffffu, sxl, c);
        tx[c] = __shfl_sync(0xffffffffu, txl, c);
    }
    int h0 = lane*4;
    float4 bsv = *(const float4*)(bs + h0);
    float4 btv = *(const float4*)(bt + h0);
    float s4[4] = {bsv.x, bsv.y, bsv.z, bsv.w};
    float t4[4] = {btv.x, btv.y, btv.z, btv.w};
    #pragma unroll
    for (int c=0;c<CIN;c++){
        float4 wsv = *(const float4*)(Ws + c*HDIM + h0);
        float4 wtv = *(const float4*)(Wt + c*HDIM + h0);
        s4[0]=fmaf(sx[c],wsv.x,s4[0]); s4[1]=fmaf(sx[c],wsv.y,s4[1]);
        s4[2]=fmaf(sx[c],wsv.z,s4[2]); s4[3]=fmaf(sx[c],wsv.w,s4[3]);
        t4[0]=fmaf(tx[c],wtv.x,t4[0]); t4[1]=fmaf(tx[c],wtv.y,t4[1]);
        t4[2]=fmaf(tx[c],wtv.z,t4[2]); t4[3]=fmaf(tx[c],wtv.w,t4[3]);
    }
    float ss = span_reduce<32>(s4[0]+s4[1]+s4[2]+s4[3]);
    float ts = span_reduce<32>(t4[0]+t4[1]+t4[2]+t4[3]);
    float ms = ss*(1.0f/HDIM), mt = ts*(1.0f/HDIM);
    float ds[4], dt[4];
    float sqs = 0.f, sqt = 0.f;
    #pragma unroll
    for (int i=0;i<4;i++){
        ds[i]=s4[i]-ms; dt[i]=t4[i]-mt;
        sqs = fmaf(ds[i],ds[i],sqs); sqt = fmaf(dt[i],dt[i],sqt);
    }
    sqs = span_reduce<32>(sqs);
    sqt = span_reduce<32>(sqt);
    float rs = rsqrtf(sqs*(1.0f/HDIM)+EPSF);
    float rt = rsqrtf(sqt*(1.0f/HDIM)+EPSF);
    float4 y;
    y.x = gelu_exact(ds[0]*rs) + gelu_exact(dt[0]*rt);
    y.y = gelu_exact(ds[1]*rs) + gelu_exact(dt[1]*rt);
    y.z = gelu_exact(ds[2]*rs) + gelu_exact(dt[2]*rt);
    y.w = gelu_exact(ds[3]*rs) + gelu_exact(dt[3]*rt);
    *(float4*)(out + ((size_t)b*L + l)*HDIM + h0) = y;
}

// ================ fused hidden: GEMM(MT=32 x N=128 full-j) + bias + inorm_j + gelu ================
template<int M>
__global__ __launch_bounds__(256) void hidden_fused(const float* __restrict__ A,
                                                    const float* __restrict__ W,
                                                    const float* __restrict__ bias,
                                                    float* __restrict__ out){
    constexpr int K=HDIM, N=HDIM, MT=32, KT=16, NKT=K/KT, AST=MT+8;
    __shared__ __align__(16) float As[2][KT*AST];
    __shared__ __align__(16) float Bs[2][KT*N];
    int tid = threadIdx.x;
    int tn = tid & 31, tm = tid >> 5;
    int m0 = blockIdx.x*MT;
    int b  = blockIdx.z;
    const float* Ab = A + (size_t)b*M*K;
    int fm = tid>>2, fq = tid&3;
    {
        if (tid < 128){
            float4 pa = *(const float4*)(Ab + (size_t)(m0+fm)*K + 4*fq);
            As[0][(4*fq+0)*AST+fm]=pa.x; As[0][(4*fq+1)*AST+fm]=pa.y;
            As[0][(4*fq+2)*AST+fm]=pa.z; As[0][(4*fq+3)*AST+fm]=pa.w;
        }
        #pragma unroll
        for (int e=0;e<2;e++){
            int q = tid + e*256;
            int fk = q>>5, ff = q&31;
            *(float4*)(Bs[0] + fk*N + 4*ff) = *(const float4*)(W + (size_t)fk*N + 4*ff);
        }
    }
    __syncthreads();
    u64 acc[4][2];
    #pragma unroll
    for (int mi=0;mi<4;mi++){ acc[mi][0]=0ull; acc[mi][1]=0ull; }
    for (int kt=0; kt<NKT; kt++){
        int cur = kt & 1;
        bool hasnext = (kt+1 < NKT);
        float4 pa, pb0, pb1;
        if (hasnext){
            int kn = (kt+1)*KT;
            if (tid < 128) pa = *(const float4*)(Ab + (size_t)(m0+fm)*K + kn + 4*fq);
            { int q=tid;     int fk=q>>5, ff=q&31; pb0 = *(const float4*)(W + (size_t)(kn+fk)*N + 4*ff); }
            { int q=tid+256; int fk=q>>5, ff=q&31; pb1 = *(const float4*)(W + (size_t)(kn+fk)*N + 4*ff); }
        }
        const float* Asb = As[cur];
        const float* Bsb = Bs[cur];
        #pragma unroll
        for (int kk=0; kk<KT; kk++){
            float4 av = *(const float4*)(Asb + kk*AST + 4*tm);
            float4 bv = *(const float4*)(Bsb + kk*N + 4*tn);
            u64 b01 = pack2(bv.x, bv.y);
            u64 b23 = pack2(bv.z, bv.w);
            u64 a0 = pack2(av.x, av.x);
            u64 a1 = pack2(av.y, av.y);
            u64 a2 = pack2(av.z, av.z);
            u64 a3 = pack2(av.w, av.w);
            ffma2(acc[0][0], a0, b01, acc[0][0]); ffma2(acc[0][1], a0, b23, acc[0][1]);
            ffma2(acc[1][0], a1, b01, acc[1][0]); ffma2(acc[1][1], a1, b23, acc[1][1]);
            ffma2(acc[2][0], a2, b01, acc[2][0]); ffma2(acc[2][1], a2, b23, acc[2][1]);
            ffma2(acc[3][0], a3, b01, acc[3][0]); ffma2(acc[3][1], a3, b23, acc[3][1]);
        }
        if (hasnext){
            int nxt = cur ^ 1;
            __syncthreads();
            if (tid < 128){
                As[nxt][(4*fq+0)*AST+fm]=pa.x; As[nxt][(4*fq+1)*AST+fm]=pa.y;
                As[nxt][(4*fq+2)*AST+fm]=pa.z; As[nxt][(4*fq+3)*AST+fm]=pa.w;
            }
            { int q=tid;     int fk=q>>5, ff=q&31; *(float4*)(Bs[nxt] + fk*N + 4*ff) = pb0; }
            { int q=tid+256; int fk=q>>5, ff=q&31; *(float4*)(Bs[nxt] + fk*N + 4*ff) = pb1; }
            __syncthreads();
        }
    }
    float4 bj = *(const float4*)(bias + 4*tn);
    float* ob = out + (size_t)b*M*N;
    #pragma unroll
    for (int mi=0;mi<4;mi++){
        float v0,v1,v2,v3;
        unpack2(acc[mi][0], v0, v1);
        unpack2(acc[mi][1], v2, v3);
        v0+=bj.x; v1+=bj.y; v2+=bj.z; v3+=bj.w;
        float mean = span_reduce<32>(v0+v1+v2+v3)*(1.0f/N);
        float d0=v0-mean, d1=v1-mean, d2=v2-mean, d3=v3-mean;
        float var = span_reduce<32>(fmaf(d0,d0,fmaf(d1,d1,fmaf(d2,d2,d3*d3))))*(1.0f/N);
        float rv = rsqrtf(var+EPSF);
        float4 o;
        o.x=gelu_exact(d0*rv); o.y=gelu_exact(d1*rv);
        o.z=gelu_exact(d2*rv); o.w=gelu_exact(d3*rv);
        *(float4*)(ob + (size_t)(m0 + 4*tm + mi)*N + 4*tn) = o;
    }
}

// ================ fused lookback: GEMM(full-N tile) + bias + inorm_j + gelu + transpose ================
template<int N, int K>
__global__ __launch_bounds__(256) void lookback_fused(const float* __restrict__ A,
                                                      const float* __restrict__ W,
                                                      const float* __restrict__ bias,
                                                      float* __restrict__ out){
    constexpr int M=HDIM, NQJ=N/4, MT=4096/N, KT=16, NKT=K/KT, AST=MT+8, TSS=MT+8;
    constexpr int AQ = MT/4;
    __shared__ __align__(16) float As[2][KT*AST];
    __shared__ __align__(16) float Bs[2][KT*N];
    __shared__ __align__(16) float Ts[N*TSS];
    int tid = threadIdx.x;
    int tn = tid % NQJ, tm = tid / NQJ;
    int m0 = blockIdx.x*MT;
    int b  = blockIdx.z;
    const float* Ab = A + (size_t)b*K*M;
    {
        #pragma unroll
        for (int e=tid; e<KT*AQ; e+=256){
            int fk = e/AQ, ff = e%AQ;
            *(float4*)(As[0] + fk*AST + 4*ff) = *(const float4*)(Ab + (size_t)fk*M + m0 + 4*ff);
        }
        #pragma unroll
        for (int e=tid; e<KT*N/4; e+=256){
            int fk = e/(N/4), ff = e%(N/4);
            *(float4*)(Bs[0] + fk*N + 4*ff) = *(const float4*)(W + (size_t)fk*N + 4*ff);
        }
    }
    __syncthreads();
    u64 acc[4][2];
    #pragma unroll
    for (int mi=0;mi<4;mi++){ acc[mi][0]=0ull; acc[mi][1]=0ull; }
    for (int kt=0; kt<NKT; kt++){
        int cur = kt & 1;
        bool hasnext = (kt+1 < NKT);
        float4 pa[(KT*AQ+255)/256], pb[(KT*N/4+255)/256];
        if (hasnext){
            int kn = (kt+1)*KT;
            #pragma unroll
            for (int e=0;e<(KT*AQ+255)/256;e++){
                int q = tid + e*256;
                if (q < KT*AQ){
                    int fk=q/AQ, ff=q%AQ;
                    pa[e] = *(const float4*)(Ab + (size_t)(kn+fk)*M + m0 + 4*ff);
                }
            }
            #pragma unroll
            for (int e=0;e<(KT*N/4+255)/256;e++){
                int q = tid + e*256;
                if (q < KT*N/4){
                    int fk=q/(N/4), ff=q%(N/4);
                    pb[e] = *(const float4*)(W + (size_t)(kn+fk)*N + 4*ff);
                }
            }
        }
        const float* Asb = As[cur];
        const float* Bsb = Bs[cur];
        #pragma unroll
        for (int kk=0; kk<KT; kk++){
            float4 av = *(const float4*)(Asb + kk*AST + 4*tm);
            float4 bv = *(const float4*)(Bsb + kk*N + 4*tn);
            u64 b01 = pack2(bv.x, bv.y);
            u64 b23 = pack2(bv.z, bv.w);
            u64 a0 = pack2(av.x, av.x);
            u64 a1 = pack2(av.y, av.y);
            u64 a2 = pack2(av.z, av.z);
            u64 a3 = pack2(av.w, av.w);
            ffma2(acc[0][0], a0, b01, acc[0][0]); ffma2(acc[0][1], a0, b23, acc[0][1]);
            ffma2(acc[1][0], a1, b01, acc[1][0]); ffma2(acc[1][1], a1, b23, acc[1][1]);
            ffma2(acc[2][0], a2, b01, acc[2][0]); ffma2(acc[2][1], a2, b23, acc[2][1]);
            ffma2(acc[3][0], a3, b01, acc[3][0]); ffma2(acc[3][1], a3, b23, acc[3][1]);
        }
        if (hasnext){
            int nxt = cur ^ 1;
            __syncthreads();
            #pragma unroll
            for (int e=0;e<(KT*AQ+255)/256;e++){
                int q = tid + e*256;
                if (q < KT*AQ){
                    int fk=q/AQ, ff=q%AQ;
                    *(float4*)(As[nxt] + fk*AST + 4*ff) = pa[e];
                }
            }
            #pragma unroll
            for (int e=0;e<(KT*N/4+255)/256;e++){
                int q = tid + e*256;
                if (q < KT*N/4){
                    int fk=q/(N/4), ff=q%(N/4);
                    *(float4*)(Bs[nxt] + fk*N + 4*ff) = pb[e];
                }
            }
            __syncthreads();
        }
    }
    float4 bj = *(const float4*)(bias + 4*tn);
    #pragma unroll
    for (int mi=0;mi<4;mi++){
        float v0,v1,v2,v3;
        unpack2(acc[mi][0], v0, v1);
        unpack2(acc[mi][1], v2, v3);
        v0+=bj.x; v1+=bj.y; v2+=bj.z; v3+=bj.w;
        float mean = span_reduce<NQJ>(v0+v1+v2+v3)*(1.0f/N);
        float d0=v0-mean, d1=v1-mean, d2=v2-mean, d3=v3-mean;
        float var = span_reduce<NQJ>(fmaf(d0,d0,fmaf(d1,d1,fmaf(d2,d2,d3*d3))))*(1.0f/N);
        float rv = rsqrtf(var+EPSF);
        int h = 4*tm + mi;
        Ts[(4*tn+0)*TSS + h] = gelu_exact(d0*rv);
        Ts[(4*tn+1)*TSS + h] = gelu_exact(d1*rv);
        Ts[(4*tn+2)*TSS + h] = gelu_exact(d2*rv);
        Ts[(4*tn+3)*TSS + h] = gelu_exact(d3*rv);
    }
    __syncthreads();
    #pragma unroll
    for (int e=tid; e<N*AQ; e+=256){
        int j = e/AQ, hq = e%AQ;
        float4 v = *(const float4*)(Ts + j*TSS + 4*hq);
        *(float4*)(out + ((size_t)b*N + j)*HDIM + m0 + 4*hq) = v;
    }
}

// ================ generic GEMM (lb1): D_z[m][n] = sum_k A_b[k][m]*B[k][n] ================
template<int M, int N, int K, int KS>
__global__ __launch_bounds__(256) void gemm_kernel(const float* __restrict__ A,
                                                   const float* __restrict__ B,
                                                   float* __restrict__ D){
    constexpr int MT=64, NT=64, KT=16;
    constexpr int KC = K/KS;
    constexpr int NKT = KC/KT;
    constexpr int AST = MT+4;
    __shared__ __align__(16) float As[2][KT*AST];
    __shared__ __align__(16) float Bs[2][KT*NT];
    int tid = threadIdx.x;
    int tn = tid & 15, tm = tid >> 4;
    int m0 = blockIdx.x * MT, n0 = blockIdx.y * NT;
    int z = blockIdx.z;
    int b = z / KS, ks = z % KS;
    int k0 = ks * KC;
    const float* Ab = A + (size_t)b*K*M;
    int fk = tid >> 4, ff = tid & 15;
    {
        float4 pa = *(const float4*)(Ab + (size_t)(k0 + fk)*M + m0 + 4*ff);
        float4 pb = *(const float4*)(B + (size_t)(k0 + fk)*N + n0 + 4*ff);
        *(float4*)(As[0] + fk*AST + 4*ff) = pa;
        *(float4*)(Bs[0] + fk*NT + 4*ff) = pb;
    }
    __syncthreads();
    u64 acc[4][2];
    #pragma unroll
    for (int mi=0;mi<4;mi++){ acc[mi][0]=0ull; acc[mi][1]=0ull; }
    for (int kt=0; kt<NKT; kt++){
        int cur = kt & 1;
        bool hasnext = (kt+1 < NKT);
        float4 pa, pb;
        if (hasnext){
            int kn = k0 + (kt+1)*KT;
            pa = *(const float4*)(Ab + (size_t)(kn + fk)*M + m0 + 4*ff);
            pb = *(const float4*)(B + (size_t)(kn + fk)*N + n0 + 4*ff);
        }
        const float* Asb = As[cur];
        const float* Bsb = Bs[cur];
        #pragma unroll
        for (int kk=0; kk<KT; kk++){
            float4 av = *(const float4*)(Asb + kk*AST + 4*tm);
            float4 bv = *(const float4*)(Bsb + kk*NT + 4*tn);
            u64 b01 = pack2(bv.x, bv.y);
            u64 b23 = pack2(bv.z, bv.w);
            u64 a0 = pack2(av.x, av.x);
            u64 a1 = pack2(av.y, av.y);
            u64 a2 = pack2(av.z, av.z);
            u64 a3 = pack2(av.w, av.w);
            ffma2(acc[0][0], a0, b01, acc[0][0]); ffma2(acc[0][1], a0, b23, acc[0][1]);
            ffma2(acc[1][0], a1, b01, acc[1][0]); ffma2(acc[1][1], a1, b23, acc[1][1]);
            ffma2(acc[2][0], a2, b01, acc[2][0]); ffma2(acc[2][1], a2, b23, acc[2][1]);
            ffma2(acc[3][0], a3, b01, acc[3][0]); ffma2(acc[3][1], a3, b23, acc[3][1]);
        }
        if (hasnext){
            int nxt = cur ^ 1;
            __syncthreads();
            *(float4*)(As[nxt] + fk*AST + 4*ff) = pa;
            *(float4*)(Bs[nxt] + fk*NT + 4*ff) = pb;
            __syncthreads();
        }
    }
    float* Dz = D + (size_t)(ks*BNUM + b) * M * N;
    #pragma unroll
    for (int mi=0; mi<4; mi++){
        float4 o;
        unpack2(acc[mi][0], o.x, o.y);
        unpack2(acc[mi][1], o.z, o.w);
        *(float4*)(Dz + (size_t)(m0 + 4*tm + mi)*N + n0 + 4*tn) = o;
    }
}

// ---------------- lookback finalize (lb1 only) ----------------
template<int LOUT, int KS>
__global__ void lookback_finalize(const float* __restrict__ part, const float* __restrict__ bias,
                                  float* __restrict__ out){
    int t = threadIdx.x;
    int h0 = blockIdx.x*4;
    int b  = blockIdx.y;
    __shared__ float rbuf[(LOUT/32)*4];
    float bj = bias[t];
    float val[4];
    #pragma unroll
    for (int h=0;h<4;h++){
        float s = bj;
        #pragma unroll
        for (int ks=0;ks<KS;ks++)
            s += part[((size_t)(ks*BNUM + b)*HDIM + h0 + h)*LOUT + t];
        val[h]=s;
    }
    float v[4] = {val[0],val[1],val[2],val[3]};
    grp_reduce4<LOUT>(v, rbuf, t);
    float d[4];
    #pragma unroll
    for (int h=0;h<4;h++) d[h] = val[h] - v[h]*(1.0f/LOUT);
    float v2[4] = {d[0]*d[0], d[1]*d[1], d[2]*d[2], d[3]*d[3]};
    grp_reduce4<LOUT>(v2, rbuf, t);
    float4 o;
    o.x = gelu_exact(d[0]*rsqrtf(v2[0]*(1.0f/LOUT)+EPSF));
    o.y = gelu_exact(d[1]*rsqrtf(v2[1]*(1.0f/LOUT)+EPSF));
    o.z = gelu_exact(d[2]*rsqrtf(v2[2]*(1.0f/LOUT)+EPSF));
    o.w = gelu_exact(d[3]*rsqrtf(v2[3]*(1.0f/LOUT)+EPSF));
    *(float4*)(out + ((size_t)b*LOUT + t)*HDIM + h0) = o;
}

// ---------------- logits ----------------
__global__ void logits_kernel(const float* __restrict__ o, const float* __restrict__ Wr,
                              const float* __restrict__ br, float* __restrict__ logits){
    int b = blockIdx.x, tid = threadIdx.x;
    float acc[8];
    #pragma unroll
    for (int r=0;r<8;r++) acc[r]=0.f;
    for (int i=tid; i<8192; i+=256){
        float x = o[(size_t)b*8192 + i];
        const float4* w4 = reinterpret_cast<const float4*>(Wr + (size_t)i*8);
        float4 wa = w4[0], wb = w4[1];
        acc[0]=fmaf(x,wa.x,acc[0]); acc[1]=fmaf(x,wa.y,acc[1]);
        acc[2]=fmaf(x,wa.z,acc[2]); acc[3]=fmaf(x,wa.w,acc[3]);
        acc[4]=fmaf(x,wb.x,acc[4]); acc[5]=fmaf(x,wb.y,acc[5]);
        acc[6]=fmaf(x,wb.z,acc[6]); acc[7]=fmaf(x,wb.w,acc[7]);
    }
    __shared__ float sh[8*8];
    #pragma unroll
    for (int r=0;r<8;r++) acc[r] = span_reduce<32>(acc[r]);
    int w=tid>>5, lane=tid&31;
    if (lane==0){
        #pragma unroll
        for (int r=0;r<8;r++) sh[r*8+w]=acc[r];
    }
    __syncthreads();
    if (tid<8){
        float s=br[tid];
        #pragma unroll
        for (int ww=0;ww<8;ww++) s+=sh[tid*8+ww];
        logits[b*8+tid]=s;
    }
}

// ---------------- final contraction, regime-grouped; gumbel computed in-block ----------------
template<int NP>
__device__ __forceinline__ void fp_body(const u64* __restrict__ es2,
                                        const float* __restrict__ P,
                                        float* __restrict__ partial,
                                        const int* __restrict__ bl,
                                        int nb, int chunk, int t){
    u64 acc[NP];
    #pragma unroll
    for (int q=0;q<NP;q++) acc[q]=0ull;
    #pragma unroll 8
    for (int nh=0; nh<256; nh++){
        float pv = P[(size_t)nh*OUTC];
        u64 pp = pack2(pv, pv);
        const u64* row = es2 + nh*16;
        #pragma unroll
        for (int p=0;p<NP/2;p++){
            ulonglong2 rr = *(const ulonglong2*)(row + 2*p);
            ffma2(acc[2*p],   rr.x, pp, acc[2*p]);
            ffma2(acc[2*p+1], rr.y, pp, acc[2*p+1]);
        }
        if (NP & 1)
            ffma2(acc[NP-1], row[NP-1], pp, acc[NP-1]);
    }
    #pragma unroll
    for (int q=0;q<NP;q++){
        float lo, hi; unpack2(acc[q], lo, hi);
        partial[((size_t)bl[2*q]*NCHUNK + chunk)*OUTC + t] = lo;
        if (2*q+1 < nb)
            partial[((size_t)bl[2*q+1]*NCHUNK + chunk)*OUTC + t] = hi;
    }
}

__global__ void final_partial(const float* __restrict__ est, const float* __restrict__ proto,
                              const float* __restrict__ logits,
                              float* __restrict__ partial){
    int chunk = blockIdx.x, r = blockIdx.y, t = threadIdx.x;  // 192 threads
    __shared__ float g[BNUM*RNUM];
    __shared__ int sreg[BNUM];
    __shared__ int bl[BNUM];
    __shared__ int snb;
    // recompute gumbel + regime selection in-block (deterministic threefry)
    for (int e = t; e < BNUM*RNUM; e += OUTC) g[e] = gumbel_idx((uint32_t)e);
    __syncthreads();
    if (t < BNUM){
        float mx = -1e30f; int am = 0;
        #pragma unroll
        for (int rr=0;rr<8;rr++){
            float z = logits[t*8+rr] + g[t*8+rr];
            if (z > mx){ mx=z; am=rr; }
        }
        sreg[t] = am;
    }
    __syncthreads();
    if (t == 0){
        int c = 0;
        for (int b=0;b<BNUM;b++)
            if (sreg[b] == r) bl[c++] = b;
        snb = c;
    }
    __syncthreads();
    int nb = snb;
    if (nb == 0) return;
    int npair = (nb+1)>>1;
    __shared__ __align__(16) u64 es2[256*16];
    int nh0 = chunk*256;
    for (int q=0;q<npair;q++){
        int b0 = bl[2*q];
        bool has1 = (2*q+1) < nb;
        const float* e0 = est + (size_t)b0*NHTOT + nh0;
        const float* e1 = has1 ? est + (size_t)bl[2*q+1]*NHTOT + nh0 : e0;
        for (int nh=t; nh<256; nh+=192){
            float lo = e0[nh];
            float hi = has1 ? e1[nh] : 0.f;
            es2[nh*16+q] = pack2(lo, hi);
        }
    }
    __syncthreads();
    const float* P = proto + ((size_t)r*NHTOT + nh0)*OUTC + t;
    switch(npair){
        case 1:  fp_body<1>(es2,P,partial,bl,nb,chunk,t); break;
        case 2:  fp_body<2 >(es2,P,partial,bl,nb,chunk,t); break;
        case 3:  fp_body<3 >(es2,P,partial,bl,nb,chunk,t); break;
        case 4:  fp_body<4 >(es2,P,partial,bl,nb,chunk,t); break;
        case 5:  fp_body<5 >(es2,P,partial,bl,nb,chunk,t); break;
        case 6:  fp_body<6 >(es2,P,partial,bl,nb,chunk,t); break;
        case 7:  fp_body<7 >(es2,P,partial,bl,nb,chunk,t); break;
        case 8:  fp_body<8 >(es2,P,partial,bl,nb,chunk,t); break;
        case 9:  fp_body<9 >(es2,P,partial,bl,nb,chunk,t); break;
        case 10: fp_body<10>(es2,P,partial,bl,nb,chunk,t); break;
        case 11: fp_body<11>(es2,P,partial,bl,nb,chunk,t); break;
        case 12: fp_body<12>(es2,P,partial,bl,nb,chunk,t); break;
        case 13: fp_body<13>(es2,P,partial,bl,nb,chunk,t); break;
        case 14: fp_body<14>(es2,P,partial,bl,nb,chunk,t); break;
        case 15: fp_body<15>(es2,P,partial,bl,nb,chunk,t); break;
        default: fp_body<16>(es2,P,partial,bl,nb,chunk,t); break;
    }
}

__global__ void final_softmax(const float* __restrict__ partial, const float* __restrict__ logits,
                              float* __restrict__ out){
    int b = blockIdx.x, t = threadIdx.x;  // 192 threads
    __shared__ float gz[8];
    __shared__ float swsel;
    if (t < 8) gz[t] = logits[b*8+t] + gumbel_idx((uint32_t)(b*8+t));
    __syncthreads();
    if (t == 0){
        float mx = gz[0];
        #pragma unroll
        for (int r=1;r<8;r++) mx = fmaxf(mx, gz[r]);
        float sum = 0.f;
        #pragma unroll
        for (int r=0;r<8;r++) sum += expf(gz[r]-mx);
        float y = 1.0f/sum;
        swsel = (1.0f - y) + y;
    }
    float s = 0.f;
    #pragma unroll 8
    for (int ch=0; ch<NCHUNK; ch++) s += partial[((size_t)b*NCHUNK+ch)*OUTC + t];
    __syncthreads();
    s *= swsel;
    __shared__ float shm[6], shs[6];
    float m = s;
    #pragma unroll
    for (int o=16;o;o>>=1) m = fmaxf(m, __shfl_xor_sync(0xffffffffu, m, o));
    if ((t&31)==0) shm[t>>5]=m;
    __syncthreads();
    m = shm[0];
    #pragma unroll
    for (int w=1;w<6;w++) m = fmaxf(m, shm[w]);
    float e = expf(s-m);
    float su = span_reduce<32>(e);
    if ((t&31)==0) shs[t>>5]=su;
    __syncthreads();
    su = 0.f;
    #pragma unroll
    for (int w=0;w<6;w++) su += shs[w];
    out[(size_t)b*OUTC + t] = e/su;
}

// ---------------- launch ----------------
extern "C" void kernel_launch(void* const* d_in, const int* in_sizes, int n_in,
                              void* d_out, int out_size){
    (void)in_sizes; (void)n_in; (void)out_size;
    const float* in_lt = (const float*)d_in[0];
    const float* in_st = (const float*)d_in[1];
    const float* Ws  = (const float*)d_in[2];  const float* bs  = (const float*)d_in[3];
    const float* Wt  = (const float*)d_in[4];  const float* bt  = (const float*)d_in[5];
    const float* Wh1 = (const float*)d_in[6];  const float* bh1 = (const float*)d_in[7];
    const float* Wl1 = (const float*)d_in[8];  const float* bl1 = (const float*)d_in[9];
    const float* Wh2 = (const float*)d_in[10]; const float* bh2 = (const float*)d_in[11];
    const float* Wl2 = (const float*)d_in[12]; const float* bl2 = (const float*)d_in[13];
    const float* Wh3 = (const float*)d_in[14]; const float* bh3 = (const float*)d_in[15];
    const float* Wl3 = (const float*)d_in[16]; const float* bl3 = (const float*)d_in[17];
    const float* Wr  = (const float*)d_in[18]; const float* br  = (const float*)d_in[19];
    const float* proto = (const float*)d_in[20];

    float *bufA, *bufB, *est, *gbuf, *logits, *partial;
    cudaGetSymbolAddress((void**)&bufA,    d_bufA);
    cudaGetSymbolAddress((void**)&bufB,    d_bufB);
    cudaGetSymbolAddress((void**)&est,     d_est);
    cudaGetSymbolAddress((void**)&gbuf,    d_gbuf);
    cudaGetSymbolAddress((void**)&logits,  d_logits);
    cudaGetSymbolAddress((void**)&partial, d_partial);

    // merged encode (lt + st segments)
    encode_kernel<<<dim3(LLT/4 + LST/4, BNUM), 128>>>(in_lt, in_st, Ws, bs, Wt, bt, bufA, est);

    // hidden1 fused: M=512 -> bufB
    hidden_fused<512><<<dim3(16,1,BNUM), 256>>>(bufA, Wh1, bh1, bufB);
    // lookback1: M=128(h), N=256(j), K=512(l), KS=4 -> gbuf -> finalize -> bufA
    gemm_kernel<128,256,512,4><<<dim3(2,4,BNUM*4), 256>>>(bufB, Wl1, gbuf);
    lookback_finalize<256,4><<<dim3(HDIM/4,BNUM), 256>>>(gbuf, bl1, bufA);

    // hidden2 fused: M=256
    hidden_fused<256><<<dim3(8,1,BNUM), 256>>>(bufA, Wh2, bh2, bufB);
    // lookback2 fused: N=128, K=256
    lookback_fused<128,256><<<dim3(4,1,BNUM), 256>>>(bufB, Wl2, bl2, bufA);

    // hidden3 fused: M=128
    hidden_fused<128><<<dim3(4,1,BNUM), 256>>>(bufA, Wh3, bh3, bufB);
    // lookback3 fused: N=64, K=128
    lookback_fused<64,128><<<dim3(2,1,BNUM), 256>>>(bufB, Wl3, bl3, bufA);

    logits_kernel<<<BNUM, 256>>>(bufA, Wr, br, logits);

    final_partial<<<dim3(NCHUNK,RNUM), OUTC>>>(est, proto, logits, partial);
    final_softmax<<<BNUM, OUTC>>>(partial, logits, (float*)d_out);
}

// round 16
// speedup vs baseline: 1.0996x; 1.0101x over previous
#include <cuda_runtime.h>
#include <math.h>
#include <stdint.h>

#define BNUM 32
#define LLT 512
#define LST 128
#define CIN 9
#define HDIM 128
#define RNUM 8
#define KWIN 25
#define PADW 12
#define EPSF 1e-5f
#define OUTC 192   // M*3
#define NHTOT 16384  // LST*HDIM
#define NCHUNK 64    // nh chunks of 256

typedef unsigned long long u64;

// -------- scratch (static device, no allocs) --------
__device__ float d_bufA[BNUM*LLT*HDIM];
__device__ float d_bufB[BNUM*LLT*HDIM];
__device__ float d_est [BNUM*LST*HDIM];
__device__ float d_gbuf[4*BNUM*HDIM*256];   // K-split partials for lb1, 16MB
__device__ float d_logits[BNUM*RNUM];
__device__ float d_partial[BNUM*NCHUNK*OUTC];

// -------- f32x2 packed math helpers --------
__device__ __forceinline__ u64 pack2(float lo, float hi){
    u64 d;
    asm("mov.b64 %0, {%1, %2};" : "=l"(d)
        : "r"(__float_as_uint(lo)), "r"(__float_as_uint(hi)));
    return d;
}
__device__ __forceinline__ void unpack2(u64 v, float& lo, float& hi){
    uint32_t a, b;
    asm("mov.b64 {%0, %1}, %2;" : "=r"(a), "=r"(b) : "l"(v));
    lo = __uint_as_float(a); hi = __uint_as_float(b);
}
__device__ __forceinline__ void ffma2(u64& d, u64 a, u64 b, u64 c){
    asm("fma.rn.f32x2 %0, %1, %2, %3;" : "=l"(d) : "l"(a), "l"(b), "l"(c));
}

__device__ __forceinline__ float gelu_exact(float x){
    return 0.5f*x*(1.0f+erff(x*0.7071067811865476f));
}

// shuffle-reduce a value over SPAN contiguous lanes (SPAN = power of 2 <= 32)
template<int SPAN>
__device__ __forceinline__ float span_reduce(float v){
    #pragma unroll
    for (int o=SPAN/2; o; o>>=1) v += __shfl_xor_sync(0xffffffffu, v, o);
    return v;
}

// reduce 4 values over the NQ threads of each tid-contiguous group (32/64/128/256)
template<int NQ>
__device__ __forceinline__ void grp_reduce4(float v[4], float* buf, int tid){
    #pragma unroll
    for (int i=0;i<4;i++) v[i] = span_reduce<32>(v[i]);
    if (NQ > 32){
        constexpr int NWG = NQ/32;
        int wid = tid>>5, lane = tid&31;
        if (lane==0){
            #pragma unroll
            for (int i=0;i<4;i++) buf[wid*4+i] = v[i];
        }
        __syncthreads();
        int gw0 = (wid/NWG)*NWG;
        #pragma unroll
        for (int i=0;i<4;i++){
            float s = 0.f;
            #pragma unroll
            for (int w=0;w<NWG;w++) s += buf[(gw0+w)*4+i];
            v[i] = s;
        }
        __syncthreads();
    }
}

// -------- exact JAX threefry2x32 (partitionable) gumbel --------
__device__ __forceinline__ uint32_t rotl32(uint32_t x,int r){ return (x<<r)|(x>>(32-r)); }
__device__ __forceinline__ float gumbel_idx(uint32_t idx){
    uint32_t x0 = 0u, x1 = idx;
    const uint32_t k0=0u, k1=42u, k2=k0^k1^0x1BD11BDAu;
    x0+=k0; x1+=k1;
    #define TFR(r) { x0+=x1; x1=rotl32(x1,r); x1^=x0; }
    TFR(13)TFR(15)TFR(26)TFR(6)   x0+=k1; x1+=k2+1u;
    TFR(17)TFR(29)TFR(16)TFR(24)  x0+=k2; x1+=k0+2u;
    TFR(13)TFR(15)TFR(26)TFR(6)   x0+=k0; x1+=k1+3u;
    TFR(17)TFR(29)TFR(16)TFR(24)  x0+=k1; x1+=k2+4u;
    TFR(13)TFR(15)TFR(26)TFR(6)   x0+=k2; x1+=k0+5u;
    #undef TFR
    uint32_t bits = x0 ^ x1;
    const float tiny = 1.17549435e-38f;
    float f = __uint_as_float((bits>>9)|0x3f800000u) - 1.0f;
    float u = fmaxf(tiny, f + tiny);
    return -logf(-logf(u));
}

// ---------------- encode (merged lt+st): warp-per-l ----------------
__global__ void encode_kernel(const float* __restrict__ in_lt, const float* __restrict__ in_st,
                              const float* __restrict__ Ws, const float* __restrict__ bs,
                              const float* __restrict__ Wt, const float* __restrict__ bt,
                              float* __restrict__ out_lt, float* __restrict__ out_st){
    int b = blockIdx.y;
    int w = threadIdx.x >> 5, lane = threadIdx.x & 31;
    const float* in; float* out; int L; int lx;
    if (blockIdx.x < LLT/4){ in = in_lt; out = out_lt; L = LLT; lx = blockIdx.x; }
    else                   { in = in_st; out = out_st; L = LST; lx = blockIdx.x - LLT/4; }
    int l = lx*4 + w;
    const float* base = in + (size_t)b*L*CIN;
    float sxl = 0.f, txl = 0.f;
    if (lane < CIN){
        int c = lane;
        float x0 = base[c];
        float xl = base[l*CIN + c];
        float sum = 0.f;
        #pragma unroll
        for (int k=0; k<KWIN; k++){
            int l2 = l - PADW + k;
            l2 = l2 < 0 ? 0 : (l2 > L-1 ? L-1 : l2);
            sum += base[l2*CIN + c];
        }
        float mavg = sum*(1.0f/KWIN);
        sxl = xl - mavg;
        txl = mavg - x0;
    }
    float sx[CIN], tx[CIN];
    #pragma unroll
    for (int c=0;c<CIN;c++){
        sx[c] = __shfl_sync(0xffffffffu, sxl, c);
        tx[c] = __shfl_sync(0xffffffffu, txl, c);
    }
    int h0 = lane*4;
    float4 bsv = *(const float4*)(bs + h0);
    float4 btv = *(const float4*)(bt + h0);
    float s4[4] = {bsv.x, bsv.y, bsv.z, bsv.w};
    float t4[4] = {btv.x, btv.y, btv.z, btv.w};
    #pragma unroll
    for (int c=0;c<CIN;c++){
        float4 wsv = *(const float4*)(Ws + c*HDIM + h0);
        float4 wtv = *(const float4*)(Wt + c*HDIM + h0);
        s4[0]=fmaf(sx[c],wsv.x,s4[0]); s4[1]=fmaf(sx[c],wsv.y,s4[1]);
        s4[2]=fmaf(sx[c],wsv.z,s4[2]); s4[3]=fmaf(sx[c],wsv.w,s4[3]);
        t4[0]=fmaf(tx[c],wtv.x,t4[0]); t4[1]=fmaf(tx[c],wtv.y,t4[1]);
        t4[2]=fmaf(tx[c],wtv.z,t4[2]); t4[3]=fmaf(tx[c],wtv.w,t4[3]);
    }
    float ss = span_reduce<32>(s4[0]+s4[1]+s4[2]+s4[3]);
    float ts = span_reduce<32>(t4[0]+t4[1]+t4[2]+t4[3]);
    float ms = ss*(1.0f/HDIM), mt = ts*(1.0f/HDIM);
    float ds[4], dt[4];
    float sqs = 0.f, sqt = 0.f;
    #pragma unroll
    for (int i=0;i<4;i++){
        ds[i]=s4[i]-ms; dt[i]=t4[i]-mt;
        sqs = fmaf(ds[i],ds[i],sqs); sqt = fmaf(dt[i],dt[i],sqt);
    }
    sqs = span_reduce<32>(sqs);
    sqt = span_reduce<32>(sqt);
    float rs = rsqrtf(sqs*(1.0f/HDIM)+EPSF);
    float rt = rsqrtf(sqt*(1.0f/HDIM)+EPSF);
    float4 y;
    y.x = gelu_exact(ds[0]*rs) + gelu_exact(dt[0]*rt);
    y.y = gelu_exact(ds[1]*rs) + gelu_exact(dt[1]*rt);
    y.z = gelu_exact(ds[2]*rs) + gelu_exact(dt[2]*rt);
    y.w = gelu_exact(ds[3]*rs) + gelu_exact(dt[3]*rt);
    *(float4*)(out + ((size_t)b*L + l)*HDIM + h0) = y;
}

// ================ fused hidden: GEMM(MT=32 x N=128 full-j) + bias + inorm_j + gelu ================
template<int M>
__global__ __launch_bounds__(256) void hidden_fused(const float* __restrict__ A,
                                                    const float* __restrict__ W,
                                                    const float* __restrict__ bias,
                                                    float* __restrict__ out){
    constexpr int K=HDIM, N=HDIM, MT=32, KT=16, NKT=K/KT, AST=MT+8;
    __shared__ __align__(16) float As[2][KT*AST];
    __shared__ __align__(16) float Bs[2][KT*N];
    int tid = threadIdx.x;
    int tn = tid & 31, tm = tid >> 5;
    int m0 = blockIdx.x*MT;
    int b  = blockIdx.z;
    const float* Ab = A + (size_t)b*M*K;
    int fm = tid>>2, fq = tid&3;
    {
        if (tid < 128){
            float4 pa = *(const float4*)(Ab + (size_t)(m0+fm)*K + 4*fq);
            As[0][(4*fq+0)*AST+fm]=pa.x; As[0][(4*fq+1)*AST+fm]=pa.y;
            As[0][(4*fq+2)*AST+fm]=pa.z; As[0][(4*fq+3)*AST+fm]=pa.w;
        }
        #pragma unroll
        for (int e=0;e<2;e++){
            int q = tid + e*256;
            int fk = q>>5, ff = q&31;
            *(float4*)(Bs[0] + fk*N + 4*ff) = *(const float4*)(W + (size_t)fk*N + 4*ff);
        }
    }
    __syncthreads();
    u64 acc[4][2];
    #pragma unroll
    for (int mi=0;mi<4;mi++){ acc[mi][0]=0ull; acc[mi][1]=0ull; }
    for (int kt=0; kt<NKT; kt++){
        int cur = kt & 1;
        bool hasnext = (kt+1 < NKT);
        float4 pa, pb0, pb1;
        if (hasnext){
            int kn = (kt+1)*KT;
            if (tid < 128) pa = *(const float4*)(Ab + (size_t)(m0+fm)*K + kn + 4*fq);
            { int q=tid;     int fk=q>>5, ff=q&31; pb0 = *(const float4*)(W + (size_t)(kn+fk)*N + 4*ff); }
            { int q=tid+256; int fk=q>>5, ff=q&31; pb1 = *(const float4*)(W + (size_t)(kn+fk)*N + 4*ff); }
        }
        const float* Asb = As[cur];
        const float* Bsb = Bs[cur];
        #pragma unroll
        for (int kk=0; kk<KT; kk++){
            float4 av = *(const float4*)(Asb + kk*AST + 4*tm);
            float4 bv = *(const float4*)(Bsb + kk*N + 4*tn);
            u64 b01 = pack2(bv.x, bv.y);
            u64 b23 = pack2(bv.z, bv.w);
            u64 a0 = pack2(av.x, av.x);
            u64 a1 = pack2(av.y, av.y);
            u64 a2 = pack2(av.z, av.z);
            u64 a3 = pack2(av.w, av.w);
            ffma2(acc[0][0], a0, b01, acc[0][0]); ffma2(acc[0][1], a0, b23, acc[0][1]);
            ffma2(acc[1][0], a1, b01, acc[1][0]); ffma2(acc[1][1], a1, b23, acc[1][1]);
            ffma2(acc[2][0], a2, b01, acc[2][0]); ffma2(acc[2][1], a2, b23, acc[2][1]);
            ffma2(acc[3][0], a3, b01, acc[3][0]); ffma2(acc[3][1], a3, b23, acc[3][1]);
        }
        if (hasnext){
            int nxt = cur ^ 1;
            __syncthreads();
            if (tid < 128){
                As[nxt][(4*fq+0)*AST+fm]=pa.x; As[nxt][(4*fq+1)*AST+fm]=pa.y;
                As[nxt][(4*fq+2)*AST+fm]=pa.z; As[nxt][(4*fq+3)*AST+fm]=pa.w;
            }
            { int q=tid;     int fk=q>>5, ff=q&31; *(float4*)(Bs[nxt] + fk*N + 4*ff) = pb0; }
            { int q=tid+256; int fk=q>>5, ff=q&31; *(float4*)(Bs[nxt] + fk*N + 4*ff) = pb1; }
            __syncthreads();
        }
    }
    float4 bj = *(const float4*)(bias + 4*tn);
    float* ob = out + (size_t)b*M*N;
    #pragma unroll
    for (int mi=0;mi<4;mi++){
        float v0,v1,v2,v3;
        unpack2(acc[mi][0], v0, v1);
        unpack2(acc[mi][1], v2, v3);
        v0+=bj.x; v1+=bj.y; v2+=bj.z; v3+=bj.w;
        float mean = span_reduce<32>(v0+v1+v2+v3)*(1.0f/N);
        float d0=v0-mean, d1=v1-mean, d2=v2-mean, d3=v3-mean;
        float var = span_reduce<32>(fmaf(d0,d0,fmaf(d1,d1,fmaf(d2,d2,d3*d3))))*(1.0f/N);
        float rv = rsqrtf(var+EPSF);
        float4 o;
        o.x=gelu_exact(d0*rv); o.y=gelu_exact(d1*rv);
        o.z=gelu_exact(d2*rv); o.w=gelu_exact(d3*rv);
        *(float4*)(ob + (size_t)(m0 + 4*tm + mi)*N + 4*tn) = o;
    }
}

// ================ fused lookback: GEMM(full-N tile) + bias + inorm_j + gelu + transpose ================
template<int N, int K>
__global__ __launch_bounds__(256) void lookback_fused(const float* __restrict__ A,
                                                      const float* __restrict__ W,
                                                      const float* __restrict__ bias,
                                                      float* __restrict__ out){
    constexpr int M=HDIM, NQJ=N/4, MT=4096/N, KT=16, NKT=K/KT, AST=MT+8, TSS=MT+8;
    constexpr int AQ = MT/4;
    __shared__ __align__(16) float As[2][KT*AST];
    __shared__ __align__(16) float Bs[2][KT*N];
    __shared__ __align__(16) float Ts[N*TSS];
    int tid = threadIdx.x;
    int tn = tid % NQJ, tm = tid / NQJ;
    int m0 = blockIdx.x*MT;
    int b  = blockIdx.z;
    const float* Ab = A + (size_t)b*K*M;
    {
        #pragma unroll
        for (int e=tid; e<KT*AQ; e+=256){
            int fk = e/AQ, ff = e%AQ;
            *(float4*)(As[0] + fk*AST + 4*ff) = *(const float4*)(Ab + (size_t)fk*M + m0 + 4*ff);
        }
        #pragma unroll
        for (int e=tid; e<KT*N/4; e+=256){
            int fk = e/(N/4), ff = e%(N/4);
            *(float4*)(Bs[0] + fk*N + 4*ff) = *(const float4*)(W + (size_t)fk*N + 4*ff);
        }
    }
    __syncthreads();
    u64 acc[4][2];
    #pragma unroll
    for (int mi=0;mi<4;mi++){ acc[mi][0]=0ull; acc[mi][1]=0ull; }
    for (int kt=0; kt<NKT; kt++){
        int cur = kt & 1;
        bool hasnext = (kt+1 < NKT);
        float4 pa[(KT*AQ+255)/256], pb[(KT*N/4+255)/256];
        if (hasnext){
            int kn = (kt+1)*KT;
            #pragma unroll
            for (int e=0;e<(KT*AQ+255)/256;e++){
                int q = tid + e*256;
                if (q < KT*AQ){
                    int fk=q/AQ, ff=q%AQ;
                    pa[e] = *(const float4*)(Ab + (size_t)(kn+fk)*M + m0 + 4*ff);
                }
            }
            #pragma unroll
            for (int e=0;e<(KT*N/4+255)/256;e++){
                int q = tid + e*256;
                if (q < KT*N/4){
                    int fk=q/(N/4), ff=q%(N/4);
                    pb[e] = *(const float4*)(W + (size_t)(kn+fk)*N + 4*ff);
                }
            }
        }
        const float* Asb = As[cur];
        const float* Bsb = Bs[cur];
        #pragma unroll
        for (int kk=0; kk<KT; kk++){
            float4 av = *(const float4*)(Asb + kk*AST + 4*tm);
            float4 bv = *(const float4*)(Bsb + kk*N + 4*tn);
            u64 b01 = pack2(bv.x, bv.y);
            u64 b23 = pack2(bv.z, bv.w);
            u64 a0 = pack2(av.x, av.x);
            u64 a1 = pack2(av.y, av.y);
            u64 a2 = pack2(av.z, av.z);
            u64 a3 = pack2(av.w, av.w);
            ffma2(acc[0][0], a0, b01, acc[0][0]); ffma2(acc[0][1], a0, b23, acc[0][1]);
            ffma2(acc[1][0], a1, b01, acc[1][0]); ffma2(acc[1][1], a1, b23, acc[1][1]);
            ffma2(acc[2][0], a2, b01, acc[2][0]); ffma2(acc[2][1], a2, b23, acc[2][1]);
            ffma2(acc[3][0], a3, b01, acc[3][0]); ffma2(acc[3][1], a3, b23, acc[3][1]);
        }
        if (hasnext){
            int nxt = cur ^ 1;
            __syncthreads();
            #pragma unroll
            for (int e=0;e<(KT*AQ+255)/256;e++){
                int q = tid + e*256;
                if (q < KT*AQ){
                    int fk=q/AQ, ff=q%AQ;
                    *(float4*)(As[nxt] + fk*AST + 4*ff) = pa[e];
                }
            }
            #pragma unroll
            for (int e=0;e<(KT*N/4+255)/256;e++){
                int q = tid + e*256;
                if (q < KT*N/4){
                    int fk=q/(N/4), ff=q%(N/4);
                    *(float4*)(Bs[nxt] + fk*N + 4*ff) = pb[e];
                }
            }
            __syncthreads();
        }
    }
    float4 bj = *(const float4*)(bias + 4*tn);
    #pragma unroll
    for (int mi=0;mi<4;mi++){
        float v0,v1,v2,v3;
        unpack2(acc[mi][0], v0, v1);
        unpack2(acc[mi][1], v2, v3);
        v0+=bj.x; v1+=bj.y; v2+=bj.z; v3+=bj.w;
        float mean = span_reduce<NQJ>(v0+v1+v2+v3)*(1.0f/N);
        float d0=v0-mean, d1=v1-mean, d2=v2-mean, d3=v3-mean;
        float var = span_reduce<NQJ>(fmaf(d0,d0,fmaf(d1,d1,fmaf(d2,d2,d3*d3))))*(1.0f/N);
        float rv = rsqrtf(var+EPSF);
        int h = 4*tm + mi;
        Ts[(4*tn+0)*TSS + h] = gelu_exact(d0*rv);
        Ts[(4*tn+1)*TSS + h] = gelu_exact(d1*rv);
        Ts[(4*tn+2)*TSS + h] = gelu_exact(d2*rv);
        Ts[(4*tn+3)*TSS + h] = gelu_exact(d3*rv);
    }
    __syncthreads();
    #pragma unroll
    for (int e=tid; e<N*AQ; e+=256){
        int j = e/AQ, hq = e%AQ;
        float4 v = *(const float4*)(Ts + j*TSS + 4*hq);
        *(float4*)(out + ((size_t)b*N + j)*HDIM + m0 + 4*hq) = v;
    }
}

// ================ generic GEMM (lb1): D_z[m][n] = sum_k A_b[k][m]*B[k][n] ================
// __launch_bounds__(256,5): register diet (62 -> ~48) to lift occupancy cap 4 -> 5 blocks/SM.
template<int M, int N, int K, int KS>
__global__ __launch_bounds__(256, 5) void gemm_kernel(const float* __restrict__ A,
                                                      const float* __restrict__ B,
                                                      float* __restrict__ D){
    constexpr int MT=64, NT=64, KT=16;
    constexpr int KC = K/KS;
    constexpr int NKT = KC/KT;
    constexpr int AST = MT+4;
    __shared__ __align__(16) float As[2][KT*AST];
    __shared__ __align__(16) float Bs[2][KT*NT];
    int tid = threadIdx.x;
    int tn = tid & 15, tm = tid >> 4;
    int m0 = blockIdx.x * MT, n0 = blockIdx.y * NT;
    int z = blockIdx.z;
    int b = z / KS, ks = z % KS;
    int k0 = ks * KC;
    const float* Ab = A + (size_t)b*K*M;
    int fk = tid >> 4, ff = tid & 15;
    {
        float4 pa = *(const float4*)(Ab + (size_t)(k0 + fk)*M + m0 + 4*ff);
        float4 pb = *(const float4*)(B + (size_t)(k0 + fk)*N + n0 + 4*ff);
        *(float4*)(As[0] + fk*AST + 4*ff) = pa;
        *(float4*)(Bs[0] + fk*NT + 4*ff) = pb;
    }
    __syncthreads();
    u64 acc[4][2];
    #pragma unroll
    for (int mi=0;mi<4;mi++){ acc[mi][0]=0ull; acc[mi][1]=0ull; }
    for (int kt=0; kt<NKT; kt++){
        int cur = kt & 1;
        bool hasnext = (kt+1 < NKT);
        float4 pa, pb;
        if (hasnext){
            int kn = k0 + (kt+1)*KT;
            pa = *(const float4*)(Ab + (size_t)(kn + fk)*M + m0 + 4*ff);
            pb = *(const float4*)(B + (size_t)(kn + fk)*N + n0 + 4*ff);
        }
        const float* Asb = As[cur];
        const float* Bsb = Bs[cur];
        #pragma unroll
        for (int kk=0; kk<KT; kk++){
            float4 av = *(const float4*)(Asb + kk*AST + 4*tm);
            float4 bv = *(const float4*)(Bsb + kk*NT + 4*tn);
            u64 b01 = pack2(bv.x, bv.y);
            u64 b23 = pack2(bv.z, bv.w);
            u64 a0 = pack2(av.x, av.x);
            u64 a1 = pack2(av.y, av.y);
            u64 a2 = pack2(av.z, av.z);
            u64 a3 = pack2(av.w, av.w);
            ffma2(acc[0][0], a0, b01, acc[0][0]); ffma2(acc[0][1], a0, b23, acc[0][1]);
            ffma2(acc[1][0], a1, b01, acc[1][0]); ffma2(acc[1][1], a1, b23, acc[1][1]);
            ffma2(acc[2][0], a2, b01, acc[2][0]); ffma2(acc[2][1], a2, b23, acc[2][1]);
            ffma2(acc[3][0], a3, b01, acc[3][0]); ffma2(acc[3][1], a3, b23, acc[3][1]);
        }
        if (hasnext){
            int nxt = cur ^ 1;
            __syncthreads();
            *(float4*)(As[nxt] + fk*AST + 4*ff) = pa;
            *(float4*)(Bs[nxt] + fk*NT + 4*ff) = pb;
            __syncthreads();
        }
    }
    float* Dz = D + (size_t)(ks*BNUM + b) * M * N;
    #pragma unroll
    for (int mi=0; mi<4; mi++){
        float4 o;
        unpack2(acc[mi][0], o.x, o.y);
        unpack2(acc[mi][1], o.z, o.w);
        *(float4*)(Dz + (size_t)(m0 + 4*tm + mi)*N + n0 + 4*tn) = o;
    }
}

// ---------------- lookback finalize (lb1 only) ----------------
template<int LOUT, int KS>
__global__ void lookback_finalize(const float* __restrict__ part, const float* __restrict__ bias,
                                  float* __restrict__ out){
    int t = threadIdx.x;
    int h0 = blockIdx.x*4;
    int b  = blockIdx.y;
    __shared__ float rbuf[(LOUT/32)*4];
    float bj = bias[t];
    float val[4];
    #pragma unroll
    for (int h=0;h<4;h++){
        float s = bj;
        #pragma unroll
        for (int ks=0;ks<KS;ks++)
            s += part[((size_t)(ks*BNUM + b)*HDIM + h0 + h)*LOUT + t];
        val[h]=s;
    }
    float v[4] = {val[0],val[1],val[2],val[3]};
    grp_reduce4<LOUT>(v, rbuf, t);
    float d[4];
    #pragma unroll
    for (int h=0;h<4;h++) d[h] = val[h] - v[h]*(1.0f/LOUT);
    float v2[4] = {d[0]*d[0], d[1]*d[1], d[2]*d[2], d[3]*d[3]};
    grp_reduce4<LOUT>(v2, rbuf, t);
    float4 o;
    o.x = gelu_exact(d[0]*rsqrtf(v2[0]*(1.0f/LOUT)+EPSF));
    o.y = gelu_exact(d[1]*rsqrtf(v2[1]*(1.0f/LOUT)+EPSF));
    o.z = gelu_exact(d[2]*rsqrtf(v2[2]*(1.0f/LOUT)+EPSF));
    o.w = gelu_exact(d[3]*rsqrtf(v2[3]*(1.0f/LOUT)+EPSF));
    *(float4*)(out + ((size_t)b*LOUT + t)*HDIM + h0) = o;
}

// ---------------- logits ----------------
__global__ void logits_kernel(const float* __restrict__ o, const float* __restrict__ Wr,
                              const float* __restrict__ br, float* __restrict__ logits){
    int b = blockIdx.x, tid = threadIdx.x;
    float acc[8];
    #pragma unroll
    for (int r=0;r<8;r++) acc[r]=0.f;
    for (int i=tid; i<8192; i+=256){
        float x = o[(size_t)b*8192 + i];
        const float4* w4 = reinterpret_cast<const float4*>(Wr + (size_t)i*8);
        float4 wa = w4[0], wb = w4[1];
        acc[0]=fmaf(x,wa.x,acc[0]); acc[1]=fmaf(x,wa.y,acc[1]);
        acc[2]=fmaf(x,wa.z,acc[2]); acc[3]=fmaf(x,wa.w,acc[3]);
        acc[4]=fmaf(x,wb.x,acc[4]); acc[5]=fmaf(x,wb.y,acc[5]);
        acc[6]=fmaf(x,wb.z,acc[6]); acc[7]=fmaf(x,wb.w,acc[7]);
    }
    __shared__ float sh[8*8];
    #pragma unroll
    for (int r=0;r<8;r++) acc[r] = span_reduce<32>(acc[r]);
    int w=tid>>5, lane=tid&31;
    if (lane==0){
        #pragma unroll
        for (int r=0;r<8;r++) sh[r*8+w]=acc[r];
    }
    __syncthreads();
    if (tid<8){
        float s=br[tid];
        #pragma unroll
        for (int ww=0;ww<8;ww++) s+=sh[tid*8+ww];
        logits[b*8+tid]=s;
    }
}

// ---------------- final contraction, regime-grouped; gumbel computed in-block ----------------
template<int NP>
__device__ __forceinline__ void fp_body(const u64* __restrict__ es2,
                                        const float* __restrict__ P,
                                        float* __restrict__ partial,
                                        const int* __restrict__ bl,
                                        int nb, int chunk, int t){
    u64 acc[NP];
    #pragma unroll
    for (int q=0;q<NP;q++) acc[q]=0ull;
    #pragma unroll 8
    for (int nh=0; nh<256; nh++){
        float pv = P[(size_t)nh*OUTC];
        u64 pp = pack2(pv, pv);
        const u64* row = es2 + nh*16;
        #pragma unroll
        for (int p=0;p<NP/2;p++){
            ulonglong2 rr = *(const ulonglong2*)(row + 2*p);
            ffma2(acc[2*p],   rr.x, pp, acc[2*p]);
            ffma2(acc[2*p+1], rr.y, pp, acc[2*p+1]);
        }
        if (NP & 1)
            ffma2(acc[NP-1], row[NP-1], pp, acc[NP-1]);
    }
    #pragma unroll
    for (int q=0;q<NP;q++){
        float lo, hi; unpack2(acc[q], lo, hi);
        partial[((size_t)bl[2*q]*NCHUNK + chunk)*OUTC + t] = lo;
        if (2*q+1 < nb)
            partial[((size_t)bl[2*q+1]*NCHUNK + chunk)*OUTC + t] = hi;
    }
}

__global__ void final_partial(const float* __restrict__ est, const float* __restrict__ proto,
                              const float* __restrict__ logits,
                              float* __restrict__ partial){
    int chunk = blockIdx.x, r = blockIdx.y, t = threadIdx.x;  // 192 threads
    __shared__ float g[BNUM*RNUM];
    __shared__ int sreg[BNUM];
    __shared__ int bl[BNUM];
    __shared__ int snb;
    // recompute gumbel + regime selection in-block (deterministic threefry)
    for (int e = t; e < BNUM*RNUM; e += OUTC) g[e] = gumbel_idx((uint32_t)e);
    __syncthreads();
    if (t < BNUM){
        float mx = -1e30f; int am = 0;
        #pragma unroll
        for (int rr=0;rr<8;rr++){
            float z = logits[t*8+rr] + g[t*8+rr];
            if (z > mx){ mx=z; am=rr; }
        }
        sreg[t] = am;
    }
    __syncthreads();
    if (t == 0){
        int c = 0;
        for (int b=0;b<BNUM;b++)
            if (sreg[b] == r) bl[c++] = b;
        snb = c;
    }
    __syncthreads();
    int nb = snb;
    if (nb == 0) return;
    int npair = (nb+1)>>1;
    __shared__ __align__(16) u64 es2[256*16];
    int nh0 = chunk*256;
    for (int q=0;q<npair;q++){
        int b0 = bl[2*q];
        bool has1 = (2*q+1) < nb;
        const float* e0 = est + (size_t)b0*NHTOT + nh0;
        const float* e1 = has1 ? est + (size_t)bl[2*q+1]*NHTOT + nh0 : e0;
        for (int nh=t; nh<256; nh+=192){
            float lo = e0[nh];
            float hi = has1 ? e1[nh] : 0.f;
            es2[nh*16+q] = pack2(lo, hi);
        }
    }
    __syncthreads();
    const float* P = proto + ((size_t)r*NHTOT + nh0)*OUTC + t;
    switch(npair){
        case 1:  fp_body<1>(es2,P,partial,bl,nb,chunk,t); break;
        case 2:  fp_body<2 >(es2,P,partial,bl,nb,chunk,t); break;
        case 3:  fp_body<3 >(es2,P,partial,bl,nb,chunk,t); break;
        case 4:  fp_body<4 >(es2,P,partial,bl,nb,chunk,t); break;
        case 5:  fp_body<5 >(es2,P,partial,bl,nb,chunk,t); break;
        case 6:  fp_body<6 >(es2,P,partial,bl,nb,chunk,t); break;
        case 7:  fp_body<7 >(es2,P,partial,bl,nb,chunk,t); break;
        case 8:  fp_body<8 >(es2,P,partial,bl,nb,chunk,t); break;
        case 9:  fp_body<9 >(es2,P,partial,bl,nb,chunk,t); break;
        case 10: fp_body<10>(es2,P,partial,bl,nb,chunk,t); break;
        case 11: fp_body<11>(es2,P,partial,bl,nb,chunk,t); break;
        case 12: fp_body<12>(es2,P,partial,bl,nb,chunk,t); break;
        case 13: fp_body<13>(es2,P,partial,bl,nb,chunk,t); break;
        case 14: fp_body<14>(es2,P,partial,bl,nb,chunk,t); break;
        case 15: fp_body<15>(es2,P,partial,bl,nb,chunk,t); break;
        default: fp_body<16>(es2,P,partial,bl,nb,chunk,t); break;
    }
}

__global__ void final_softmax(const float* __restrict__ partial, const float* __restrict__ logits,
                              float* __restrict__ out){
    int b = blockIdx.x, t = threadIdx.x;  // 192 threads
    __shared__ float gz[8];
    __shared__ float swsel;
    if (t < 8) gz[t] = logits[b*8+t] + gumbel_idx((uint32_t)(b*8+t));
    __syncthreads();
    if (t == 0){
        float mx = gz[0];
        #pragma unroll
        for (int r=1;r<8;r++) mx = fmaxf(mx, gz[r]);
        float sum = 0.f;
        #pragma unroll
        for (int r=0;r<8;r++) sum += expf(gz[r]-mx);
        float y = 1.0f/sum;
        swsel = (1.0f - y) + y;
    }
    float s = 0.f;
    #pragma unroll 8
    for (int ch=0; ch<NCHUNK; ch++) s += partial[((size_t)b*NCHUNK+ch)*OUTC + t];
    __syncthreads();
    s *= swsel;
    __shared__ float shm[6], shs[6];
    float m = s;
    #pragma unroll
    for (int o=16;o;o>>=1) m = fmaxf(m, __shfl_xor_sync(0xffffffffu, m, o));
    if ((t&31)==0) shm[t>>5]=m;
    __syncthreads();
    m = shm[0];
    #pragma unroll
    for (int w=1;w<6;w++) m = fmaxf(m, shm[w]);
    float e = expf(s-m);
    float su = span_reduce<32>(e);
    if ((t&31)==0) shs[t>>5]=su;
    __syncthreads();
    su = 0.f;
    #pragma unroll
    for (int w=0;w<6;w++) su += shs[w];
    out[(size_t)b*OUTC + t] = e/su;
}

// ---------------- launch ----------------
extern "C" void kernel_launch(void* const* d_in, const int* in_sizes, int n_in,
                              void* d_out, int out_size){
    (void)in_sizes; (void)n_in; (void)out_size;
    const float* in_lt = (const float*)d_in[0];
    const float* in_st = (const float*)d_in[1];
    const float* Ws  = (const float*)d_in[2];  const float* bs  = (const float*)d_in[3];
    const float* Wt  = (const float*)d_in[4];  const float* bt  = (const float*)d_in[5];
    const float* Wh1 = (const float*)d_in[6];  const float* bh1 = (const float*)d_in[7];
    const float* Wl1 = (const float*)d_in[8];  const float* bl1 = (const float*)d_in[9];
    const float* Wh2 = (const float*)d_in[10]; const float* bh2 = (const float*)d_in[11];
    const float* Wl2 = (const float*)d_in[12]; const float* bl2 = (const float*)d_in[13];
    const float* Wh3 = (const float*)d_in[14]; const float* bh3 = (const float*)d_in[15];
    const float* Wl3 = (const float*)d_in[16]; const float* bl3 = (const float*)d_in[17];
    const float* Wr  = (const float*)d_in[18]; const float* br  = (const float*)d_in[19];
    const float* proto = (const float*)d_in[20];

    float *bufA, *bufB, *est, *gbuf, *logits, *partial;
    cudaGetSymbolAddress((void**)&bufA,    d_bufA);
    cudaGetSymbolAddress((void**)&bufB,    d_bufB);
    cudaGetSymbolAddress((void**)&est,     d_est);
    cudaGetSymbolAddress((void**)&gbuf,    d_gbuf);
    cudaGetSymbolAddress((void**)&logits,  d_logits);
    cudaGetSymbolAddress((void**)&partial, d_partial);

    // merged encode (lt + st segments)
    encode_kernel<<<dim3(LLT/4 + LST/4, BNUM), 128>>>(in_lt, in_st, Ws, bs, Wt, bt, bufA, est);

    // hidden1 fused: M=512 -> bufB
    hidden_fused<512><<<dim3(16,1,BNUM), 256>>>(bufA, Wh1, bh1, bufB);
    // lookback1: M=128(h), N=256(j), K=512(l), KS=4 -> gbuf -> finalize -> bufA
    gemm_kernel<128,256,512,4><<<dim3(2,4,BNUM*4), 256>>>(bufB, Wl1, gbuf);
    lookback_finalize<256,4><<<dim3(HDIM/4,BNUM), 256>>>(gbuf, bl1, bufA);

    // hidden2 fused: M=256
    hidden_fused<256><<<dim3(8,1,BNUM), 256>>>(bufA, Wh2, bh2, bufB);
    // lookback2 fused: N=128, K=256
    lookback_fused<128,256><<<dim3(4,1,BNUM), 256>>>(bufB, Wl2, bl2, bufA);

    // hidden3 fused: M=128
    hidden_fused<128><<<dim3(4,1,BNUM), 256>>>(bufA, Wh3, bh3, bufB);
    // lookback3 fused: N=64, K=128
    lookback_fused<64,128><<<dim3(2,1,BNUM), 256>>>(bufB, Wl3, bl3, bufA);

    logits_kernel<<<BNUM, 256>>>(bufA, Wr, br, logits);

    final_partial<<<dim3(NCHUNK,RNUM), OUTC>>>(est, proto, logits, partial);
    final_softmax<<<BNUM, OUTC>>>(partial, logits, (float*)d_out);
}